// round 14
// baseline (speedup 1.0000x reference)
#include <cuda_runtime.h>
#include <cuda_bf16.h>
#include <cstdint>

// ---------------------------------------------------------------------------
// Problem constants
// ---------------------------------------------------------------------------
constexpr int B_  = 4;
constexpr int S_  = 2048;
constexpr int D_  = 1024;
constexpr int H_  = 16;
constexpr int DH_ = 64;
constexpr int M_TOT = B_ * S_;                    // 8192
constexpr size_t QKV_STRIDE = (size_t)M_TOT * D_; // 8388608
constexpr size_t W_STRIDE   = (size_t)D_ * D_;    // 1048576

// Softmax scale folded into Q at projection time: 1/sqrt(64) * log2(e)
constexpr float QSCALE = 0.18033688011112042f;

// Scratch (device globals: allocation-free rule)
__device__ float g_cos[S_ * (DH_ / 2)];
__device__ float g_sin[S_ * (DH_ / 2)];
__device__ __nv_bfloat16 g_ah[M_TOT * D_];        // hi split: x, later attention out
__device__ __nv_bfloat16 g_al[M_TOT * D_];        // lo split
__device__ __nv_bfloat16 g_wh[4 * W_STRIDE];      // hi split of wq|wk|wv|wo
__device__ __nv_bfloat16 g_wl[4 * W_STRIDE];      // lo split
__device__ __nv_bfloat16 g_qkh[2 * M_TOT * D_];   // hi split of roped (scaled) q|k
__device__ __nv_bfloat16 g_qkl[2 * M_TOT * D_];   // lo split
__device__ __nv_bfloat16 g_vth[M_TOT * D_];       // V^T hi: [bh][d][s]
__device__ __nv_bfloat16 g_vtl[M_TOT * D_];       // V^T lo

// Work-pool state (re-zeroed by prep each graph replay)
__device__ int g_pool;
__device__ int g_qkv_done[4];
__device__ int g_attn_done[64];

// ---------------------------------------------------------------------------
// helpers
// ---------------------------------------------------------------------------
__device__ __forceinline__ uint32_t smem_to_u32(const void* smem_ptr) {
    uint32_t addr;
    asm("{ .reg .u64 tmp; cvta.to.shared.u64 tmp, %1; cvt.u32.u64 %0, tmp; }"
        : "=r"(addr) : "l"(smem_ptr));
    return addr;
}

__device__ __forceinline__ void cp_async16(uint32_t saddr, const void* gptr) {
    asm volatile("cp.async.cg.shared.global [%0], [%1], 16;"
                 :: "r"(saddr), "l"(gptr) : "memory");
}
__device__ __forceinline__ void cp_commit() {
    asm volatile("cp.async.commit_group;" ::: "memory");
}
template <int N>
__device__ __forceinline__ void cp_wait() {
    asm volatile("cp.async.wait_group %0;" :: "n"(N) : "memory");
}

__device__ __forceinline__ void ldmx4(uint32_t* r, uint32_t addr) {
    asm volatile("ldmatrix.sync.aligned.m8n8.x4.shared.b16 {%0,%1,%2,%3}, [%4];"
                 : "=r"(r[0]), "=r"(r[1]), "=r"(r[2]), "=r"(r[3]) : "r"(addr));
}

__device__ __forceinline__ void mma_bf16(float* c, const uint32_t* a,
                                         uint32_t b0, uint32_t b1) {
    asm volatile(
        "mma.sync.aligned.m16n8k16.row.col.f32.bf16.bf16.f32 "
        "{%0,%1,%2,%3}, {%4,%5,%6,%7}, {%8,%9}, {%0,%1,%2,%3};"
        : "+f"(c[0]), "+f"(c[1]), "+f"(c[2]), "+f"(c[3])
        : "r"(a[0]), "r"(a[1]), "r"(a[2]), "r"(a[3]), "r"(b0), "r"(b1));
}

__device__ __forceinline__ float ex2f(float x) {
    float r; asm("ex2.approx.f32 %0, %1;" : "=f"(r) : "f"(x)); return r;
}

__device__ __forceinline__ void split2pack(float x, float y, uint32_t& h, uint32_t& l) {
    asm("cvt.rn.bf16x2.f32 %0, %1, %2;" : "=r"(h) : "f"(y), "f"(x));
    float fx = __uint_as_float(h << 16);
    float fy = __uint_as_float(h & 0xffff0000u);
    float lx = x - fx, ly = y - fy;
    asm("cvt.rn.bf16x2.f32 %0, %1, %2;" : "=r"(l) : "f"(ly), "f"(lx));
}

__device__ __forceinline__ void red_release(int* p, int v) {
    asm volatile("red.release.gpu.global.add.s32 [%0], %1;" :: "l"(p), "r"(v) : "memory");
}
__device__ __forceinline__ int ld_acquire(int* p) {
    int v;
    asm volatile("ld.acquire.gpu.global.s32 %0, [%1];" : "=r"(v) : "l"(p) : "memory");
    return v;
}

// ---------------------------------------------------------------------------
// Fused prep: counter reset + RoPE table (fp32 trig) + x split + w split
// ---------------------------------------------------------------------------
__global__ void prep_kernel(const float* __restrict__ x,
                            const float* __restrict__ w0, const float* __restrict__ w1,
                            const float* __restrict__ w2, const float* __restrict__ w3)
{
    const int bid = blockIdx.x, tid = threadIdx.x;
    if (bid < 256) {
        if (bid == 0) {           // reset pool state for this replay
            if (tid == 0) g_pool = 0;
            if (tid < 4)  g_qkv_done[tid] = 0;
            if (tid < 64) g_attn_done[tid] = 0;
        }
        int idx = bid * 256 + tid;   // 65536
        int s = idx >> 5, i = idx & 31;
        float inv = exp2f(-(float)(2 * i) * (13.28771237954945f / 64.0f));
        float ang = (float)s * inv;
        float sv, cv;
        sincosf(ang, &sv, &cv);
        g_cos[idx] = cv;
        g_sin[idx] = sv;
    } else if (bid < 256 + 2048) {
        int base = (bid - 256) * 1024 + tid;
        float4 v[4];
#pragma unroll
        for (int r = 0; r < 4; r++)
            v[r] = reinterpret_cast<const float4*>(x)[base + r * 256];
#pragma unroll
        for (int r = 0; r < 4; r++) {
            uint32_t h0, l0, h1, l1;
            split2pack(v[r].x, v[r].y, h0, l0);
            split2pack(v[r].z, v[r].w, h1, l1);
            reinterpret_cast<uint2*>(g_ah)[base + r * 256] = make_uint2(h0, h1);
            reinterpret_cast<uint2*>(g_al)[base + r * 256] = make_uint2(l0, l1);
        }
    } else {
        const int n4w = (int)(W_STRIDE / 4);
        int gbase = (bid - 2304) * 1024 + tid;
        int z = gbase / n4w;
        int rbase = gbase - z * n4w;
        const float* src = (z == 0) ? w0 : (z == 1) ? w1 : (z == 2) ? w2 : w3;
        float4 v[4];
#pragma unroll
        for (int r = 0; r < 4; r++)
            v[r] = reinterpret_cast<const float4*>(src)[rbase + r * 256];
#pragma unroll
        for (int r = 0; r < 4; r++) {
            uint32_t h0, l0, h1, l1;
            split2pack(v[r].x, v[r].y, h0, l0);
            split2pack(v[r].z, v[r].w, h1, l1);
            reinterpret_cast<uint2*>(g_wh)[gbase + r * 256] = make_uint2(h0, h1);
            reinterpret_cast<uint2*>(g_wl)[gbase + r * 256] = make_uint2(l0, l1);
        }
    }
}

// ---------------------------------------------------------------------------
// GEMM tile body (validated R13 arithmetic, verbatim).
// mode 0: q (RoPE+QSCALE->bf16), 1: k (RoPE->bf16), 2: v (V^T bf16), 3: wo (fp32).
// Weight index == mode (wq|wk|wv|wo layout in g_wh/g_wl).
// ---------------------------------------------------------------------------
__device__ __forceinline__ void gemm_tile(char* smem, int m0, int n0, int mode,
                                          float* __restrict__ out)
{
    const uint32_t sb = smem_to_u32(smem);
    const int tid = threadIdx.x, lane = tid & 31, wid = tid >> 5;
    const __nv_bfloat16* WhZ = g_wh + (size_t)mode * W_STRIDE;
    const __nv_bfloat16* WlZ = g_wl + (size_t)mode * W_STRIDE;
    const int wm = (wid >> 1) * 32, wn = (wid & 1) * 64;

    auto issue_loads = [&](int s, int buf) {
        const int k0 = s * 32;
        uint32_t base = sb + buf * 32768u;
#pragma unroll
        for (int i = 0; i < 2; i++) {
            int idx = tid + 256 * i;
            int row = idx >> 2, ch = idx & 3;
            uint32_t sw = (uint32_t)row * 64 + ((uint32_t)(ch ^ ((row >> 1) & 3)) << 4);
            size_t ga = (size_t)(m0 + row) * 1024 + k0 + ch * 8;
            size_t gb = (size_t)(n0 + row) * 1024 + k0 + ch * 8;
            cp_async16(base + sw,          g_ah + ga);
            cp_async16(base + 8192 + sw,   g_al + ga);
            cp_async16(base + 16384 + sw,  WhZ  + gb);
            cp_async16(base + 24576 + sw,  WlZ  + gb);
        }
        cp_commit();
    };

    float c[2][8][4];
#pragma unroll
    for (int i = 0; i < 2; i++)
#pragma unroll
        for (int j = 0; j < 8; j++)
#pragma unroll
            for (int q = 0; q < 4; q++) c[i][j][q] = 0.f;

    const int mrowA0 = wm + ((lane >> 3) & 1) * 8 + (lane & 7);
    const int kcA    = (lane >> 4) & 1;
    const int nrowB0 = wn + ((lane >> 4) & 1) * 8 + (lane & 7);
    const int kcB    = (lane >> 3) & 1;

    issue_loads(0, 0);
    issue_loads(1, 1);

    for (int s = 0; s < 32; s++) {
        const int buf = s % 3;
        if (s + 1 < 32) cp_wait<1>(); else cp_wait<0>();
        __syncthreads();
        if (s + 2 < 32) issue_loads(s + 2, (s + 2) % 3);

        const uint32_t abase = sb + buf * 32768u;
        const uint32_t bbase = abase + 16384u;
#pragma unroll
        for (int kc2 = 0; kc2 < 2; kc2++) {
            uint32_t ah[2][4], al[2][4];
#pragma unroll
            for (int i = 0; i < 2; i++) {
                int mr = mrowA0 + 16 * i;
                int unit = (kc2 << 1) | kcA;
                uint32_t addr = abase + mr * 64 +
                    ((uint32_t)(unit ^ ((mr >> 1) & 3)) << 4);
                ldmx4(ah[i], addr);
                ldmx4(al[i], addr + 8192);
            }
#pragma unroll
            for (int j = 0; j < 4; j++) {
                int nr = nrowB0 + 16 * j;
                int unit = (kc2 << 1) | kcB;
                uint32_t baddr = bbase + nr * 64 +
                    ((uint32_t)(unit ^ ((nr >> 1) & 3)) << 4);
                uint32_t bh[4], bl[4];
                ldmx4(bh, baddr);
                ldmx4(bl, baddr + 8192);
#pragma unroll
                for (int i = 0; i < 2; i++) {
                    mma_bf16(c[i][2 * j],     ah[i], bh[0], bh[1]);
                    mma_bf16(c[i][2 * j + 1], ah[i], bh[2], bh[3]);
                    mma_bf16(c[i][2 * j],     al[i], bh[0], bh[1]);
                    mma_bf16(c[i][2 * j + 1], al[i], bh[2], bh[3]);
                    mma_bf16(c[i][2 * j],     ah[i], bl[0], bl[1]);
                    mma_bf16(c[i][2 * j + 1], ah[i], bl[2], bl[3]);
                }
            }
        }
    }

    const int g = lane >> 2, tig = lane & 3;

    if (mode < 2) {
        const float qs = (mode == 0) ? QSCALE : 1.0f;
        __nv_bfloat16* DhZ = g_qkh + (size_t)mode * QKV_STRIDE;
        __nv_bfloat16* DlZ = g_qkl + (size_t)mode * QKV_STRIDE;
#pragma unroll
        for (int i = 0; i < 2; i++) {
            int mrow = m0 + wm + 16 * i + g;
            int s0 = mrow & 2047, s1 = (mrow + 8) & 2047;
#pragma unroll
            for (int nt = 0; nt < 8; nt++) {
                int col = n0 + wn + nt * 8 + tig * 2;
                int fi = (col & 63) >> 1;
                float cv0 = g_cos[s0 * 32 + fi], sv0 = g_sin[s0 * 32 + fi];
                float cv1 = g_cos[s1 * 32 + fi], sv1 = g_sin[s1 * 32 + fi];
                float r0 = (c[i][nt][0] * cv0 - c[i][nt][1] * sv0) * qs;
                float r1 = (c[i][nt][0] * sv0 + c[i][nt][1] * cv0) * qs;
                float r2 = (c[i][nt][2] * cv1 - c[i][nt][3] * sv1) * qs;
                float r3 = (c[i][nt][2] * sv1 + c[i][nt][3] * cv1) * qs;
                uint32_t h, l;
                size_t idx0 = (size_t)mrow * 1024 + col;
                split2pack(r0, r1, h, l);
                *reinterpret_cast<uint32_t*>(DhZ + idx0) = h;
                *reinterpret_cast<uint32_t*>(DlZ + idx0) = l;
                size_t idx1 = idx0 + (size_t)8 * 1024;
                split2pack(r2, r3, h, l);
                *reinterpret_cast<uint32_t*>(DhZ + idx1) = h;
                *reinterpret_cast<uint32_t*>(DlZ + idx1) = l;
            }
        }
    } else if (mode == 2) {
        // V tile -> transpose via smem -> V^T bf16 hi/lo [bh][d][s]
        __syncthreads();
        float* ts = reinterpret_cast<float*>(smem);   // [128][132]
#pragma unroll
        for (int i = 0; i < 2; i++) {
            int r0 = wm + 16 * i + g;
#pragma unroll
            for (int nt = 0; nt < 8; nt++) {
                int cc = wn + nt * 8 + tig * 2;
                *reinterpret_cast<float2*>(&ts[r0 * 132 + cc]) =
                    make_float2(c[i][nt][0], c[i][nt][1]);
                *reinterpret_cast<float2*>(&ts[(r0 + 8) * 132 + cc]) =
                    make_float2(c[i][nt][2], c[i][nt][3]);
            }
        }
        __syncthreads();
        const int col = tid & 127;
        const int shalf = (tid >> 7) * 64;
        const int b = m0 >> 11;
        const int sg = (m0 & 2047) + shalf;
        const int hd = (n0 + col) >> 6, d = (n0 + col) & 63;
        size_t obase = ((size_t)((b * 16 + hd) * 64 + d)) * 2048 + sg;
        __nv_bfloat16* vh = g_vth + obase;
        __nv_bfloat16* vl = g_vtl + obase;
#pragma unroll
        for (int t8 = 0; t8 < 8; t8++) {
            uint32_t hb[4], lb[4];
#pragma unroll
            for (int p = 0; p < 4; p++) {
                int sr = shalf + t8 * 8 + 2 * p;
                float v0 = ts[sr * 132 + col];
                float v1 = ts[(sr + 1) * 132 + col];
                split2pack(v0, v1, hb[p], lb[p]);
            }
            *reinterpret_cast<uint4*>(vh + t8 * 8) = make_uint4(hb[0], hb[1], hb[2], hb[3]);
            *reinterpret_cast<uint4*>(vl + t8 * 8) = make_uint4(lb[0], lb[1], lb[2], lb[3]);
        }
    } else {
        // fp32 epilogue (final projection)
#pragma unroll
        for (int i = 0; i < 2; i++) {
            int mrow = m0 + wm + 16 * i + g;
#pragma unroll
            for (int nt = 0; nt < 8; nt++) {
                int col = n0 + wn + nt * 8 + tig * 2;
                float* p = out + (size_t)mrow * 1024 + col;
                *reinterpret_cast<float2*>(p) = make_float2(c[i][nt][0], c[i][nt][1]);
                *reinterpret_cast<float2*>(p + 8 * 1024) = make_float2(c[i][nt][2], c[i][nt][3]);
            }
        }
    }
}

// ---------------------------------------------------------------------------
// Attention tile body (validated R13 arithmetic, verbatim).
// ---------------------------------------------------------------------------
constexpr uint32_t QH_O = 0, QL_O = 16384, KV_O = 32768;

__device__ __forceinline__ void attn_tile(char* smem, int qt, int bh)
{
    const uint32_t sb = smem_to_u32(smem);
    const int tid = threadIdx.x, lane = tid & 31, w = tid >> 5;
    const int b = bh >> 4, h = bh & 15;
    const int q0 = qt * 128;
    const int njk = 2 * qt + 2;

    auto issue_kv = [&](int jk, int buf) {
        uint32_t base = sb + KV_O + buf * 32768u;
#pragma unroll
        for (int i = 0; i < 2; i++) {
            int idx = tid + 256 * i;
            int r = idx >> 3, ch = idx & 7;
            uint32_t sw = r * 128 + ((ch ^ (r & 7)) << 4);
            size_t gk = QKV_STRIDE + (size_t)(b * 2048 + jk * 64 + r) * 1024 + h * 64 + ch * 8;
            cp_async16(base + sw,         g_qkh + gk);
            cp_async16(base + 8192 + sw,  g_qkl + gk);
            size_t gv = ((size_t)bh * 64 + r) * 2048 + jk * 64 + ch * 8;
            cp_async16(base + 16384 + sw, g_vth + gv);
            cp_async16(base + 24576 + sw, g_vtl + gv);
        }
        cp_commit();
    };

#pragma unroll
    for (int i = 0; i < 4; i++) {
        int idx = tid + 256 * i;
        int r = idx >> 3, ch = idx & 7;
        size_t gq = (size_t)(b * 2048 + q0 + r) * 1024 + h * 64 + ch * 8;
        uint32_t sw = r * 128 + ((ch ^ (r & 7)) << 4);
        cp_async16(sb + QH_O + sw, g_qkh + gq);
        cp_async16(sb + QL_O + sw, g_qkl + gq);
    }
    cp_commit();
    issue_kv(0, 0);

    float o[8][4];
#pragma unroll
    for (int nt = 0; nt < 8; nt++)
#pragma unroll
        for (int q = 0; q < 4; q++) o[nt][q] = 0.f;
    float m0 = -1e30f, m1 = -1e30f, l0 = 0.f, l1 = 0.f;

    const int g_  = lane >> 2, tig = lane & 3;
    const int mrA = w * 16 + ((lane >> 3) & 1) * 8 + (lane & 7);
    const int kcA = (lane >> 4) & 1;
    const int nrB = ((lane >> 4) & 1) * 8 + (lane & 7);
    const int kcB = (lane >> 3) & 1;
    const int row0 = q0 + w * 16 + g_;
    const int wrow_max = q0 + w * 16 + 15;

    for (int jk = 0; jk < njk; jk++) {
        const int buf = jk & 1;
        cp_wait<0>();
        __syncthreads();
        if (jk + 1 < njk) issue_kv(jk + 1, buf ^ 1);

        if (jk * 64 > wrow_max) continue;   // exact no-op: skip

        const uint32_t kbase = sb + KV_O + buf * 32768u;
        const uint32_t vbase = kbase + 16384u;

        float c[8][4];
#pragma unroll
        for (int nt = 0; nt < 8; nt++)
#pragma unroll
            for (int q = 0; q < 4; q++) c[nt][q] = 0.f;

#pragma unroll
        for (int k16 = 0; k16 < 4; k16++) {
            uint32_t ah[4], al[4];
            uint32_t aaddr = sb + QH_O + mrA * 128 +
                ((((k16 << 1) | kcA) ^ (mrA & 7)) << 4);
            ldmx4(ah, aaddr);
            ldmx4(al, aaddr + (QL_O - QH_O));
#pragma unroll
            for (int j = 0; j < 4; j++) {
                int nr = 16 * j + nrB;
                uint32_t baddr = kbase + nr * 128 +
                    ((((k16 << 1) | kcB) ^ (nr & 7)) << 4);
                uint32_t bhh[4], bll[4];
                ldmx4(bhh, baddr);
                ldmx4(bll, baddr + 8192);
                mma_bf16(c[2 * j],     ah, bhh[0], bhh[1]);
                mma_bf16(c[2 * j + 1], ah, bhh[2], bhh[3]);
                mma_bf16(c[2 * j],     al, bhh[0], bhh[1]);
                mma_bf16(c[2 * j + 1], al, bhh[2], bhh[3]);
                mma_bf16(c[2 * j],     ah, bll[0], bll[1]);
                mma_bf16(c[2 * j + 1], ah, bll[2], bll[3]);
            }
        }

        if (jk >= 2 * qt) {
#pragma unroll
            for (int nt = 0; nt < 8; nt++) {
                int colg = jk * 64 + 8 * nt + 2 * tig;
                if (colg     > row0)     c[nt][0] = -1e30f;
                if (colg + 1 > row0)     c[nt][1] = -1e30f;
                if (colg     > row0 + 8) c[nt][2] = -1e30f;
                if (colg + 1 > row0 + 8) c[nt][3] = -1e30f;
            }
        }

        float rm0 = -1e30f, rm1 = -1e30f;
#pragma unroll
        for (int nt = 0; nt < 8; nt++) {
            rm0 = fmaxf(rm0, fmaxf(c[nt][0], c[nt][1]));
            rm1 = fmaxf(rm1, fmaxf(c[nt][2], c[nt][3]));
        }
        rm0 = fmaxf(rm0, __shfl_xor_sync(0xffffffffu, rm0, 1));
        rm0 = fmaxf(rm0, __shfl_xor_sync(0xffffffffu, rm0, 2));
        rm1 = fmaxf(rm1, __shfl_xor_sync(0xffffffffu, rm1, 1));
        rm1 = fmaxf(rm1, __shfl_xor_sync(0xffffffffu, rm1, 2));

        float mn0 = fmaxf(m0, rm0), mn1 = fmaxf(m1, rm1);
        float a0 = ex2f(m0 - mn0), a1 = ex2f(m1 - mn1);
        m0 = mn0; m1 = mn1;

        float rs0 = 0.f, rs1 = 0.f;
#pragma unroll
        for (int nt = 0; nt < 8; nt++) {
            c[nt][0] = ex2f(c[nt][0] - mn0);
            c[nt][1] = ex2f(c[nt][1] - mn0);
            c[nt][2] = ex2f(c[nt][2] - mn1);
            c[nt][3] = ex2f(c[nt][3] - mn1);
            rs0 += c[nt][0] + c[nt][1];
            rs1 += c[nt][2] + c[nt][3];
        }
        rs0 += __shfl_xor_sync(0xffffffffu, rs0, 1);
        rs0 += __shfl_xor_sync(0xffffffffu, rs0, 2);
        rs1 += __shfl_xor_sync(0xffffffffu, rs1, 1);
        rs1 += __shfl_xor_sync(0xffffffffu, rs1, 2);
        l0 = l0 * a0 + rs0;
        l1 = l1 * a1 + rs1;
#pragma unroll
        for (int nt = 0; nt < 8; nt++) {
            o[nt][0] *= a0; o[nt][1] *= a0;
            o[nt][2] *= a1; o[nt][3] *= a1;
        }

#pragma unroll
        for (int k16 = 0; k16 < 4; k16++) {
            uint32_t aph[4], apl[4];
            split2pack(c[2 * k16][0],     c[2 * k16][1],     aph[0], apl[0]);
            split2pack(c[2 * k16][2],     c[2 * k16][3],     aph[1], apl[1]);
            split2pack(c[2 * k16 + 1][0], c[2 * k16 + 1][1], aph[2], apl[2]);
            split2pack(c[2 * k16 + 1][2], c[2 * k16 + 1][3], aph[3], apl[3]);
#pragma unroll
            for (int j = 0; j < 4; j++) {
                int nr = 16 * j + nrB;
                uint32_t baddr = vbase + nr * 128 +
                    ((((k16 << 1) | kcB) ^ (nr & 7)) << 4);
                uint32_t vhh[4], vll[4];
                ldmx4(vhh, baddr);
                ldmx4(vll, baddr + 8192);
                mma_bf16(o[2 * j],     aph, vhh[0], vhh[1]);
                mma_bf16(o[2 * j + 1], aph, vhh[2], vhh[3]);
                mma_bf16(o[2 * j],     apl, vhh[0], vhh[1]);
                mma_bf16(o[2 * j + 1], apl, vhh[2], vhh[3]);
                mma_bf16(o[2 * j],     aph, vll[0], vll[1]);
                mma_bf16(o[2 * j + 1], aph, vll[2], vll[3]);
            }
        }
    }

    float inv0 = 1.0f / l0, inv1 = 1.0f / l1;
    size_t base0 = (size_t)(b * 2048 + row0) * 1024 + h * 64 + 2 * tig;
    size_t base1 = base0 + (size_t)8 * 1024;
#pragma unroll
    for (int nt = 0; nt < 8; nt++) {
        uint32_t hh, ll;
        split2pack(o[nt][0] * inv0, o[nt][1] * inv0, hh, ll);
        *reinterpret_cast<uint32_t*>(g_ah + base0 + 8 * nt) = hh;
        *reinterpret_cast<uint32_t*>(g_al + base0 + 8 * nt) = ll;
        split2pack(o[nt][2] * inv1, o[nt][3] * inv1, hh, ll);
        *reinterpret_cast<uint32_t*>(g_ah + base1 + 8 * nt) = hh;
        *reinterpret_cast<uint32_t*>(g_al + base1 + 8 * nt) = ll;
    }
}

// ---------------------------------------------------------------------------
// Persistent mega-kernel: one global work pool packs QKV, attention, and wo
// tiles (per batch: 384 QKV | 256 attn | 128 wo = 768). Dependencies gated by
// release/acquire counters; all waits reference strictly earlier pool entries,
// so the schedule is deadlock-free regardless of residency.
// ---------------------------------------------------------------------------
constexpr int MEGA_SMEM = 98304;

__global__ void __launch_bounds__(256, 2)
mega_kernel(float* __restrict__ out)
{
    extern __shared__ char smem[];
    __shared__ int s_idx;
    const int tid = threadIdx.x;

    for (;;) {
        __syncthreads();                      // prior tile fully done (smem reuse)
        if (tid == 0) s_idx = atomicAdd(&g_pool, 1);
        __syncthreads();
        const int idx = s_idx;
        if (idx >= 3072) return;

        const int batch = idx / 768;
        const int r = idx - batch * 768;

        if (r < 384) {
            // QKV tile: z in {0,1,2}, 16 m-tiles x 8 n-tiles per z
            int z = r >> 7, r2 = r & 127;
            int m0 = (batch * 16 + (r2 >> 3)) * 128;
            int n0 = (r2 & 7) * 128;
            gemm_tile(smem, m0, n0, z, out);
            __threadfence();
            __syncthreads();
            if (tid == 0) red_release(&g_qkv_done[batch], 1);
        } else if (r < 640) {
            // attention tile: heavy q-tiles first
            int a = r - 384;
            int qt = 15 - (a >> 4), h = a & 15;
            if (tid == 0) {
                while (ld_acquire(&g_qkv_done[batch]) < 384) __nanosleep(256);
            }
            __syncthreads();
            attn_tile(smem, qt, batch * 16 + h);
            __threadfence();
            __syncthreads();
            if (tid == 0) red_release(&g_attn_done[batch * 16 + qt], 1);
        } else {
            // wo tile: needs all 16 heads of its (batch, qt) attention rows
            int a = r - 640;
            int qt = 15 - (a >> 3), nt = a & 7;
            if (tid == 0) {
                while (ld_acquire(&g_attn_done[batch * 16 + qt]) < 16) __nanosleep(256);
            }
            __syncthreads();
            gemm_tile(smem, (batch * 16 + qt) * 128, nt * 128, 3, out);
        }
    }
}

// ---------------------------------------------------------------------------
extern "C" void kernel_launch(void* const* d_in, const int* in_sizes, int n_in,
                              void* d_out, int out_size)
{
    (void)in_sizes; (void)n_in; (void)out_size;
    const float* x  = (const float*)d_in[0];
    const float* wq = (const float*)d_in[1];
    const float* wk = (const float*)d_in[2];
    const float* wv = (const float*)d_in[3];
    const float* wo = (const float*)d_in[4];
    float* out = (float*)d_out;

    cudaFuncSetAttribute(mega_kernel, cudaFuncAttributeMaxDynamicSharedMemorySize, MEGA_SMEM);

    int nsm = 148;
    cudaDeviceGetAttribute(&nsm, cudaDevAttrMultiProcessorCount, 0);

    // Prep: counters + rope table + x/w splits
    prep_kernel<<<256 + 2048 + 1024, 256>>>(x, wq, wk, wv, wo);

    // Everything else: one persistent launch, 2 CTAs/SM
    mega_kernel<<<2 * nsm, 256, MEGA_SMEM>>>(out);
}

// round 15
// speedup vs baseline: 1.2733x; 1.2733x over previous
#include <cuda_runtime.h>
#include <cuda_bf16.h>
#include <cstdint>

// ---------------------------------------------------------------------------
// Problem constants
// ---------------------------------------------------------------------------
constexpr int B_  = 4;
constexpr int S_  = 2048;
constexpr int D_  = 1024;
constexpr int H_  = 16;
constexpr int DH_ = 64;
constexpr int M_TOT = B_ * S_;                    // 8192
constexpr size_t QKV_STRIDE = (size_t)M_TOT * D_; // 8388608
constexpr size_t W_STRIDE   = (size_t)D_ * D_;    // 1048576

// Softmax scale folded into Q at projection time: 1/sqrt(64) * log2(e)
constexpr float QSCALE = 0.18033688011112042f;

// Scratch (device globals: allocation-free rule)
__device__ float g_cos[S_ * (DH_ / 2)];
__device__ float g_sin[S_ * (DH_ / 2)];
__device__ __nv_bfloat16 g_ah[M_TOT * D_];        // hi split: x, later attention out
__device__ __nv_bfloat16 g_al[M_TOT * D_];        // lo split
__device__ __nv_bfloat16 g_wh[4 * W_STRIDE];      // hi split of wq|wk|wv|wo
__device__ __nv_bfloat16 g_wl[4 * W_STRIDE];      // lo split
__device__ __nv_bfloat16 g_qkh[2 * M_TOT * D_];   // hi split of roped (scaled) q|k
__device__ __nv_bfloat16 g_qkl[2 * M_TOT * D_];   // lo split
__device__ __nv_bfloat16 g_vth[M_TOT * D_];       // V^T hi: [bh][d][s]
__device__ __nv_bfloat16 g_vtl[M_TOT * D_];       // V^T lo

// Work-pool state (re-zeroed by prep each graph replay)
__device__ int g_pool;
__device__ int g_qkv_done[4];
__device__ int g_attn_done[64];

// ---------------------------------------------------------------------------
// helpers
// ---------------------------------------------------------------------------
__device__ __forceinline__ uint32_t smem_to_u32(const void* smem_ptr) {
    uint32_t addr;
    asm("{ .reg .u64 tmp; cvta.to.shared.u64 tmp, %1; cvt.u32.u64 %0, tmp; }"
        : "=r"(addr) : "l"(smem_ptr));
    return addr;
}

__device__ __forceinline__ void cp_async16(uint32_t saddr, const void* gptr) {
    asm volatile("cp.async.cg.shared.global [%0], [%1], 16;"
                 :: "r"(saddr), "l"(gptr) : "memory");
}
__device__ __forceinline__ void cp_commit() {
    asm volatile("cp.async.commit_group;" ::: "memory");
}
template <int N>
__device__ __forceinline__ void cp_wait() {
    asm volatile("cp.async.wait_group %0;" :: "n"(N) : "memory");
}

__device__ __forceinline__ void ldmx4(uint32_t* r, uint32_t addr) {
    asm volatile("ldmatrix.sync.aligned.m8n8.x4.shared.b16 {%0,%1,%2,%3}, [%4];"
                 : "=r"(r[0]), "=r"(r[1]), "=r"(r[2]), "=r"(r[3]) : "r"(addr));
}

__device__ __forceinline__ void mma_bf16(float* c, const uint32_t* a,
                                         uint32_t b0, uint32_t b1) {
    asm volatile(
        "mma.sync.aligned.m16n8k16.row.col.f32.bf16.bf16.f32 "
        "{%0,%1,%2,%3}, {%4,%5,%6,%7}, {%8,%9}, {%0,%1,%2,%3};"
        : "+f"(c[0]), "+f"(c[1]), "+f"(c[2]), "+f"(c[3])
        : "r"(a[0]), "r"(a[1]), "r"(a[2]), "r"(a[3]), "r"(b0), "r"(b1));
}

__device__ __forceinline__ float ex2f(float x) {
    float r; asm("ex2.approx.f32 %0, %1;" : "=f"(r) : "f"(x)); return r;
}

__device__ __forceinline__ void split2pack(float x, float y, uint32_t& h, uint32_t& l) {
    asm("cvt.rn.bf16x2.f32 %0, %1, %2;" : "=r"(h) : "f"(y), "f"(x));
    float fx = __uint_as_float(h << 16);
    float fy = __uint_as_float(h & 0xffff0000u);
    float lx = x - fx, ly = y - fy;
    asm("cvt.rn.bf16x2.f32 %0, %1, %2;" : "=r"(l) : "f"(ly), "f"(lx));
}

__device__ __forceinline__ void red_release(int* p, int v) {
    asm volatile("red.release.gpu.global.add.s32 [%0], %1;" :: "l"(p), "r"(v) : "memory");
}
__device__ __forceinline__ int ld_acquire(int* p) {
    int v;
    asm volatile("ld.acquire.gpu.global.s32 %0, [%1];" : "=r"(v) : "l"(p) : "memory");
    return v;
}

// ---------------------------------------------------------------------------
// Fused prep: counter reset + RoPE table (fp32 trig) + x split + w split
// ---------------------------------------------------------------------------
__global__ void prep_kernel(const float* __restrict__ x,
                            const float* __restrict__ w0, const float* __restrict__ w1,
                            const float* __restrict__ w2, const float* __restrict__ w3)
{
    const int bid = blockIdx.x, tid = threadIdx.x;
    if (bid < 256) {
        if (bid == 0) {           // reset pool state for this replay
            if (tid == 0) g_pool = 0;
            if (tid < 4)  g_qkv_done[tid] = 0;
            if (tid < 64) g_attn_done[tid] = 0;
        }
        int idx = bid * 256 + tid;   // 65536
        int s = idx >> 5, i = idx & 31;
        float inv = exp2f(-(float)(2 * i) * (13.28771237954945f / 64.0f));
        float ang = (float)s * inv;
        float sv, cv;
        sincosf(ang, &sv, &cv);
        g_cos[idx] = cv;
        g_sin[idx] = sv;
    } else if (bid < 256 + 2048) {
        int base = (bid - 256) * 1024 + tid;
        float4 v[4];
#pragma unroll
        for (int r = 0; r < 4; r++)
            v[r] = reinterpret_cast<const float4*>(x)[base + r * 256];
#pragma unroll
        for (int r = 0; r < 4; r++) {
            uint32_t h0, l0, h1, l1;
            split2pack(v[r].x, v[r].y, h0, l0);
            split2pack(v[r].z, v[r].w, h1, l1);
            reinterpret_cast<uint2*>(g_ah)[base + r * 256] = make_uint2(h0, h1);
            reinterpret_cast<uint2*>(g_al)[base + r * 256] = make_uint2(l0, l1);
        }
    } else {
        const int n4w = (int)(W_STRIDE / 4);
        int gbase = (bid - 2304) * 1024 + tid;
        int z = gbase / n4w;
        int rbase = gbase - z * n4w;
        const float* src = (z == 0) ? w0 : (z == 1) ? w1 : (z == 2) ? w2 : w3;
        float4 v[4];
#pragma unroll
        for (int r = 0; r < 4; r++)
            v[r] = reinterpret_cast<const float4*>(src)[rbase + r * 256];
#pragma unroll
        for (int r = 0; r < 4; r++) {
            uint32_t h0, l0, h1, l1;
            split2pack(v[r].x, v[r].y, h0, l0);
            split2pack(v[r].z, v[r].w, h1, l1);
            reinterpret_cast<uint2*>(g_wh)[gbase + r * 256] = make_uint2(h0, h1);
            reinterpret_cast<uint2*>(g_wl)[gbase + r * 256] = make_uint2(l0, l1);
        }
    }
}

// ---------------------------------------------------------------------------
// GEMM tile body (validated R13 arithmetic, verbatim).
// mode 0: q (RoPE+QSCALE->bf16), 1: k (RoPE->bf16), 2: v (V^T bf16), 3: wo (fp32).
// ---------------------------------------------------------------------------
__device__ __forceinline__ void gemm_tile(char* smem, int m0, int n0, int mode,
                                          float* __restrict__ out)
{
    const uint32_t sb = smem_to_u32(smem);
    const int tid = threadIdx.x, lane = tid & 31, wid = tid >> 5;
    const __nv_bfloat16* WhZ = g_wh + (size_t)mode * W_STRIDE;
    const __nv_bfloat16* WlZ = g_wl + (size_t)mode * W_STRIDE;
    const int wm = (wid >> 1) * 32, wn = (wid & 1) * 64;

    auto issue_loads = [&](int s, int buf) {
        const int k0 = s * 32;
        uint32_t base = sb + buf * 32768u;
#pragma unroll
        for (int i = 0; i < 2; i++) {
            int idx = tid + 256 * i;
            int row = idx >> 2, ch = idx & 3;
            uint32_t sw = (uint32_t)row * 64 + ((uint32_t)(ch ^ ((row >> 1) & 3)) << 4);
            size_t ga = (size_t)(m0 + row) * 1024 + k0 + ch * 8;
            size_t gb = (size_t)(n0 + row) * 1024 + k0 + ch * 8;
            cp_async16(base + sw,          g_ah + ga);
            cp_async16(base + 8192 + sw,   g_al + ga);
            cp_async16(base + 16384 + sw,  WhZ  + gb);
            cp_async16(base + 24576 + sw,  WlZ  + gb);
        }
        cp_commit();
    };

    float c[2][8][4];
#pragma unroll
    for (int i = 0; i < 2; i++)
#pragma unroll
        for (int j = 0; j < 8; j++)
#pragma unroll
            for (int q = 0; q < 4; q++) c[i][j][q] = 0.f;

    const int mrowA0 = wm + ((lane >> 3) & 1) * 8 + (lane & 7);
    const int kcA    = (lane >> 4) & 1;
    const int nrowB0 = wn + ((lane >> 4) & 1) * 8 + (lane & 7);
    const int kcB    = (lane >> 3) & 1;

    issue_loads(0, 0);
    issue_loads(1, 1);

    for (int s = 0; s < 32; s++) {
        const int buf = s % 3;
        if (s + 1 < 32) cp_wait<1>(); else cp_wait<0>();
        __syncthreads();
        if (s + 2 < 32) issue_loads(s + 2, (s + 2) % 3);

        const uint32_t abase = sb + buf * 32768u;
        const uint32_t bbase = abase + 16384u;
#pragma unroll
        for (int kc2 = 0; kc2 < 2; kc2++) {
            uint32_t ah[2][4], al[2][4];
#pragma unroll
            for (int i = 0; i < 2; i++) {
                int mr = mrowA0 + 16 * i;
                int unit = (kc2 << 1) | kcA;
                uint32_t addr = abase + mr * 64 +
                    ((uint32_t)(unit ^ ((mr >> 1) & 3)) << 4);
                ldmx4(ah[i], addr);
                ldmx4(al[i], addr + 8192);
            }
#pragma unroll
            for (int j = 0; j < 4; j++) {
                int nr = nrowB0 + 16 * j;
                int unit = (kc2 << 1) | kcB;
                uint32_t baddr = bbase + nr * 64 +
                    ((uint32_t)(unit ^ ((nr >> 1) & 3)) << 4);
                uint32_t bh[4], bl[4];
                ldmx4(bh, baddr);
                ldmx4(bl, baddr + 8192);
#pragma unroll
                for (int i = 0; i < 2; i++) {
                    mma_bf16(c[i][2 * j],     ah[i], bh[0], bh[1]);
                    mma_bf16(c[i][2 * j + 1], ah[i], bh[2], bh[3]);
                    mma_bf16(c[i][2 * j],     al[i], bh[0], bh[1]);
                    mma_bf16(c[i][2 * j + 1], al[i], bh[2], bh[3]);
                    mma_bf16(c[i][2 * j],     ah[i], bl[0], bl[1]);
                    mma_bf16(c[i][2 * j + 1], ah[i], bl[2], bl[3]);
                }
            }
        }
    }

    const int g = lane >> 2, tig = lane & 3;

    if (mode < 2) {
        const float qs = (mode == 0) ? QSCALE : 1.0f;
        __nv_bfloat16* DhZ = g_qkh + (size_t)mode * QKV_STRIDE;
        __nv_bfloat16* DlZ = g_qkl + (size_t)mode * QKV_STRIDE;
#pragma unroll
        for (int i = 0; i < 2; i++) {
            int mrow = m0 + wm + 16 * i + g;
            int s0 = mrow & 2047, s1 = (mrow + 8) & 2047;
#pragma unroll
            for (int nt = 0; nt < 8; nt++) {
                int col = n0 + wn + nt * 8 + tig * 2;
                int fi = (col & 63) >> 1;
                float cv0 = g_cos[s0 * 32 + fi], sv0 = g_sin[s0 * 32 + fi];
                float cv1 = g_cos[s1 * 32 + fi], sv1 = g_sin[s1 * 32 + fi];
                float r0 = (c[i][nt][0] * cv0 - c[i][nt][1] * sv0) * qs;
                float r1 = (c[i][nt][0] * sv0 + c[i][nt][1] * cv0) * qs;
                float r2 = (c[i][nt][2] * cv1 - c[i][nt][3] * sv1) * qs;
                float r3 = (c[i][nt][2] * sv1 + c[i][nt][3] * cv1) * qs;
                uint32_t h, l;
                size_t idx0 = (size_t)mrow * 1024 + col;
                split2pack(r0, r1, h, l);
                *reinterpret_cast<uint32_t*>(DhZ + idx0) = h;
                *reinterpret_cast<uint32_t*>(DlZ + idx0) = l;
                size_t idx1 = idx0 + (size_t)8 * 1024;
                split2pack(r2, r3, h, l);
                *reinterpret_cast<uint32_t*>(DhZ + idx1) = h;
                *reinterpret_cast<uint32_t*>(DlZ + idx1) = l;
            }
        }
    } else if (mode == 2) {
        __syncthreads();
        float* ts = reinterpret_cast<float*>(smem);   // [128][132]
#pragma unroll
        for (int i = 0; i < 2; i++) {
            int r0 = wm + 16 * i + g;
#pragma unroll
            for (int nt = 0; nt < 8; nt++) {
                int cc = wn + nt * 8 + tig * 2;
                *reinterpret_cast<float2*>(&ts[r0 * 132 + cc]) =
                    make_float2(c[i][nt][0], c[i][nt][1]);
                *reinterpret_cast<float2*>(&ts[(r0 + 8) * 132 + cc]) =
                    make_float2(c[i][nt][2], c[i][nt][3]);
            }
        }
        __syncthreads();
        const int col = tid & 127;
        const int shalf = (tid >> 7) * 64;
        const int b = m0 >> 11;
        const int sg = (m0 & 2047) + shalf;
        const int hd = (n0 + col) >> 6, d = (n0 + col) & 63;
        size_t obase = ((size_t)((b * 16 + hd) * 64 + d)) * 2048 + sg;
        __nv_bfloat16* vh = g_vth + obase;
        __nv_bfloat16* vl = g_vtl + obase;
#pragma unroll
        for (int t8 = 0; t8 < 8; t8++) {
            uint32_t hb[4], lb[4];
#pragma unroll
            for (int p = 0; p < 4; p++) {
                int sr = shalf + t8 * 8 + 2 * p;
                float v0 = ts[sr * 132 + col];
                float v1 = ts[(sr + 1) * 132 + col];
                split2pack(v0, v1, hb[p], lb[p]);
            }
            *reinterpret_cast<uint4*>(vh + t8 * 8) = make_uint4(hb[0], hb[1], hb[2], hb[3]);
            *reinterpret_cast<uint4*>(vl + t8 * 8) = make_uint4(lb[0], lb[1], lb[2], lb[3]);
        }
    } else {
#pragma unroll
        for (int i = 0; i < 2; i++) {
            int mrow = m0 + wm + 16 * i + g;
#pragma unroll
            for (int nt = 0; nt < 8; nt++) {
                int col = n0 + wn + nt * 8 + tig * 2;
                float* p = out + (size_t)mrow * 1024 + col;
                *reinterpret_cast<float2*>(p) = make_float2(c[i][nt][0], c[i][nt][1]);
                *reinterpret_cast<float2*>(p + 8 * 1024) = make_float2(c[i][nt][2], c[i][nt][3]);
            }
        }
    }
}

// ---------------------------------------------------------------------------
// Attention tile body (validated R13 arithmetic, verbatim).
// ---------------------------------------------------------------------------
constexpr uint32_t QH_O = 0, QL_O = 16384, KV_O = 32768;

__device__ __forceinline__ void attn_tile(char* smem, int qt, int bh)
{
    const uint32_t sb = smem_to_u32(smem);
    const int tid = threadIdx.x, lane = tid & 31, w = tid >> 5;
    const int b = bh >> 4, h = bh & 15;
    const int q0 = qt * 128;
    const int njk = 2 * qt + 2;

    auto issue_kv = [&](int jk, int buf) {
        uint32_t base = sb + KV_O + buf * 32768u;
#pragma unroll
        for (int i = 0; i < 2; i++) {
            int idx = tid + 256 * i;
            int r = idx >> 3, ch = idx & 7;
            uint32_t sw = r * 128 + ((ch ^ (r & 7)) << 4);
            size_t gk = QKV_STRIDE + (size_t)(b * 2048 + jk * 64 + r) * 1024 + h * 64 + ch * 8;
            cp_async16(base + sw,         g_qkh + gk);
            cp_async16(base + 8192 + sw,  g_qkl + gk);
            size_t gv = ((size_t)bh * 64 + r) * 2048 + jk * 64 + ch * 8;
            cp_async16(base + 16384 + sw, g_vth + gv);
            cp_async16(base + 24576 + sw, g_vtl + gv);
        }
        cp_commit();
    };

#pragma unroll
    for (int i = 0; i < 4; i++) {
        int idx = tid + 256 * i;
        int r = idx >> 3, ch = idx & 7;
        size_t gq = (size_t)(b * 2048 + q0 + r) * 1024 + h * 64 + ch * 8;
        uint32_t sw = r * 128 + ((ch ^ (r & 7)) << 4);
        cp_async16(sb + QH_O + sw, g_qkh + gq);
        cp_async16(sb + QL_O + sw, g_qkl + gq);
    }
    cp_commit();
    issue_kv(0, 0);

    float o[8][4];
#pragma unroll
    for (int nt = 0; nt < 8; nt++)
#pragma unroll
        for (int q = 0; q < 4; q++) o[nt][q] = 0.f;
    float m0 = -1e30f, m1 = -1e30f, l0 = 0.f, l1 = 0.f;

    const int g_  = lane >> 2, tig = lane & 3;
    const int mrA = w * 16 + ((lane >> 3) & 1) * 8 + (lane & 7);
    const int kcA = (lane >> 4) & 1;
    const int nrB = ((lane >> 4) & 1) * 8 + (lane & 7);
    const int kcB = (lane >> 3) & 1;
    const int row0 = q0 + w * 16 + g_;
    const int wrow_max = q0 + w * 16 + 15;

    for (int jk = 0; jk < njk; jk++) {
        const int buf = jk & 1;
        cp_wait<0>();
        __syncthreads();
        if (jk + 1 < njk) issue_kv(jk + 1, buf ^ 1);

        if (jk * 64 > wrow_max) continue;   // exact no-op: skip

        const uint32_t kbase = sb + KV_O + buf * 32768u;
        const uint32_t vbase = kbase + 16384u;

        float c[8][4];
#pragma unroll
        for (int nt = 0; nt < 8; nt++)
#pragma unroll
            for (int q = 0; q < 4; q++) c[nt][q] = 0.f;

#pragma unroll
        for (int k16 = 0; k16 < 4; k16++) {
            uint32_t ah[4], al[4];
            uint32_t aaddr = sb + QH_O + mrA * 128 +
                ((((k16 << 1) | kcA) ^ (mrA & 7)) << 4);
            ldmx4(ah, aaddr);
            ldmx4(al, aaddr + (QL_O - QH_O));
#pragma unroll
            for (int j = 0; j < 4; j++) {
                int nr = 16 * j + nrB;
                uint32_t baddr = kbase + nr * 128 +
                    ((((k16 << 1) | kcB) ^ (nr & 7)) << 4);
                uint32_t bhh[4], bll[4];
                ldmx4(bhh, baddr);
                ldmx4(bll, baddr + 8192);
                mma_bf16(c[2 * j],     ah, bhh[0], bhh[1]);
                mma_bf16(c[2 * j + 1], ah, bhh[2], bhh[3]);
                mma_bf16(c[2 * j],     al, bhh[0], bhh[1]);
                mma_bf16(c[2 * j + 1], al, bhh[2], bhh[3]);
                mma_bf16(c[2 * j],     ah, bll[0], bll[1]);
                mma_bf16(c[2 * j + 1], ah, bll[2], bll[3]);
            }
        }

        if (jk >= 2 * qt) {
#pragma unroll
            for (int nt = 0; nt < 8; nt++) {
                int colg = jk * 64 + 8 * nt + 2 * tig;
                if (colg     > row0)     c[nt][0] = -1e30f;
                if (colg + 1 > row0)     c[nt][1] = -1e30f;
                if (colg     > row0 + 8) c[nt][2] = -1e30f;
                if (colg + 1 > row0 + 8) c[nt][3] = -1e30f;
            }
        }

        float rm0 = -1e30f, rm1 = -1e30f;
#pragma unroll
        for (int nt = 0; nt < 8; nt++) {
            rm0 = fmaxf(rm0, fmaxf(c[nt][0], c[nt][1]));
            rm1 = fmaxf(rm1, fmaxf(c[nt][2], c[nt][3]));
        }
        rm0 = fmaxf(rm0, __shfl_xor_sync(0xffffffffu, rm0, 1));
        rm0 = fmaxf(rm0, __shfl_xor_sync(0xffffffffu, rm0, 2));
        rm1 = fmaxf(rm1, __shfl_xor_sync(0xffffffffu, rm1, 1));
        rm1 = fmaxf(rm1, __shfl_xor_sync(0xffffffffu, rm1, 2));

        float mn0 = fmaxf(m0, rm0), mn1 = fmaxf(m1, rm1);
        float a0 = ex2f(m0 - mn0), a1 = ex2f(m1 - mn1);
        m0 = mn0; m1 = mn1;

        float rs0 = 0.f, rs1 = 0.f;
#pragma unroll
        for (int nt = 0; nt < 8; nt++) {
            c[nt][0] = ex2f(c[nt][0] - mn0);
            c[nt][1] = ex2f(c[nt][1] - mn0);
            c[nt][2] = ex2f(c[nt][2] - mn1);
            c[nt][3] = ex2f(c[nt][3] - mn1);
            rs0 += c[nt][0] + c[nt][1];
            rs1 += c[nt][2] + c[nt][3];
        }
        rs0 += __shfl_xor_sync(0xffffffffu, rs0, 1);
        rs0 += __shfl_xor_sync(0xffffffffu, rs0, 2);
        rs1 += __shfl_xor_sync(0xffffffffu, rs1, 1);
        rs1 += __shfl_xor_sync(0xffffffffu, rs1, 2);
        l0 = l0 * a0 + rs0;
        l1 = l1 * a1 + rs1;
#pragma unroll
        for (int nt = 0; nt < 8; nt++) {
            o[nt][0] *= a0; o[nt][1] *= a0;
            o[nt][2] *= a1; o[nt][3] *= a1;
        }

#pragma unroll
        for (int k16 = 0; k16 < 4; k16++) {
            uint32_t aph[4], apl[4];
            split2pack(c[2 * k16][0],     c[2 * k16][1],     aph[0], apl[0]);
            split2pack(c[2 * k16][2],     c[2 * k16][3],     aph[1], apl[1]);
            split2pack(c[2 * k16 + 1][0], c[2 * k16 + 1][1], aph[2], apl[2]);
            split2pack(c[2 * k16 + 1][2], c[2 * k16 + 1][3], aph[3], apl[3]);
#pragma unroll
            for (int j = 0; j < 4; j++) {
                int nr = 16 * j + nrB;
                uint32_t baddr = vbase + nr * 128 +
                    ((((k16 << 1) | kcB) ^ (nr & 7)) << 4);
                uint32_t vhh[4], vll[4];
                ldmx4(vhh, baddr);
                ldmx4(vll, baddr + 8192);
                mma_bf16(o[2 * j],     aph, vhh[0], vhh[1]);
                mma_bf16(o[2 * j + 1], aph, vhh[2], vhh[3]);
                mma_bf16(o[2 * j],     apl, vhh[0], vhh[1]);
                mma_bf16(o[2 * j + 1], apl, vhh[2], vhh[3]);
                mma_bf16(o[2 * j],     aph, vll[0], vll[1]);
                mma_bf16(o[2 * j + 1], aph, vll[2], vll[3]);
            }
        }
    }

    float inv0 = 1.0f / l0, inv1 = 1.0f / l1;
    size_t base0 = (size_t)(b * 2048 + row0) * 1024 + h * 64 + 2 * tig;
    size_t base1 = base0 + (size_t)8 * 1024;
#pragma unroll
    for (int nt = 0; nt < 8; nt++) {
        uint32_t hh, ll;
        split2pack(o[nt][0] * inv0, o[nt][1] * inv0, hh, ll);
        *reinterpret_cast<uint32_t*>(g_ah + base0 + 8 * nt) = hh;
        *reinterpret_cast<uint32_t*>(g_al + base0 + 8 * nt) = ll;
        split2pack(o[nt][2] * inv1, o[nt][3] * inv1, hh, ll);
        *reinterpret_cast<uint32_t*>(g_ah + base1 + 8 * nt) = hh;
        *reinterpret_cast<uint32_t*>(g_al + base1 + 8 * nt) = ll;
    }
}

// ---------------------------------------------------------------------------
// Persistent mega-kernel, PHASE-MAJOR pool:
//   [0,1536)    : all QKV tiles, batch-major (batch 0 finishes first)
//   [1536,2560) : all attention tiles, qt descending (heavy first)
//   [2560,3072) : all wo tiles, qt descending
// Gates reference work that is nearly complete when reached, so spins are
// bounded by one tile latency; phases backfill each other's tails.
// ---------------------------------------------------------------------------
constexpr int MEGA_SMEM = 98304;

__global__ void __launch_bounds__(256, 2)
mega_kernel(float* __restrict__ out)
{
    extern __shared__ char smem[];
    __shared__ int s_idx;
    const int tid = threadIdx.x;

    for (;;) {
        __syncthreads();                      // prior tile fully done (smem reuse)
        if (tid == 0) s_idx = atomicAdd(&g_pool, 1);
        __syncthreads();
        const int idx = s_idx;
        if (idx >= 3072) return;

        if (idx < 1536) {
            // QKV tile: batch-major -> batch = idx/384
            int batch = idx / 384;
            int r = idx - batch * 384;
            int z = r >> 7, r2 = r & 127;
            int m0 = (batch * 16 + (r2 >> 3)) * 128;
            int n0 = (r2 & 7) * 128;
            gemm_tile(smem, m0, n0, z, out);
            __threadfence();
            __syncthreads();
            if (tid == 0) red_release(&g_qkv_done[batch], 1);
        } else if (idx < 2560) {
            // attention tile: qt descending, then bh
            int a = idx - 1536;                 // 0..1023
            int qt = 15 - (a >> 6);
            int bh = a & 63;
            int batch = bh >> 4;
            if (tid == 0) {
                while (ld_acquire(&g_qkv_done[batch]) < 384) __nanosleep(256);
            }
            __syncthreads();
            attn_tile(smem, qt, bh);
            __threadfence();
            __syncthreads();
            if (tid == 0) red_release(&g_attn_done[batch * 16 + qt], 1);
        } else {
            // wo tile: qt descending; needs all 16 heads of its (batch, qt)
            int a = idx - 2560;                 // 0..511
            int qt = 15 - (a >> 5);
            int e = a & 31;
            int batch = e >> 3, nt = e & 7;
            if (tid == 0) {
                while (ld_acquire(&g_attn_done[batch * 16 + qt]) < 16) __nanosleep(256);
            }
            __syncthreads();
            gemm_tile(smem, (batch * 16 + qt) * 128, nt * 128, 3, out);
        }
    }
}

// ---------------------------------------------------------------------------
extern "C" void kernel_launch(void* const* d_in, const int* in_sizes, int n_in,
                              void* d_out, int out_size)
{
    (void)in_sizes; (void)n_in; (void)out_size;
    const float* x  = (const float*)d_in[0];
    const float* wq = (const float*)d_in[1];
    const float* wk = (const float*)d_in[2];
    const float* wv = (const float*)d_in[3];
    const float* wo = (const float*)d_in[4];
    float* out = (float*)d_out;

    cudaFuncSetAttribute(mega_kernel, cudaFuncAttributeMaxDynamicSharedMemorySize, MEGA_SMEM);

    int nsm = 148;
    cudaDeviceGetAttribute(&nsm, cudaDevAttrMultiProcessorCount, 0);

    // Prep: counters + rope table + x/w splits
    prep_kernel<<<256 + 2048 + 1024, 256>>>(x, wq, wk, wv, wo);

    // Everything else: one persistent launch, 2 CTAs/SM
    mega_kernel<<<2 * nsm, 256, MEGA_SMEM>>>(out);
}

// round 16
// speedup vs baseline: 1.4223x; 1.1170x over previous
#include <cuda_runtime.h>
#include <cuda_bf16.h>
#include <cstdint>

// ---------------------------------------------------------------------------
// Problem constants
// ---------------------------------------------------------------------------
constexpr int B_  = 4;
constexpr int S_  = 2048;
constexpr int D_  = 1024;
constexpr int H_  = 16;
constexpr int DH_ = 64;
constexpr int M_TOT = B_ * S_;                    // 8192
constexpr size_t QKV_STRIDE = (size_t)M_TOT * D_; // 8388608
constexpr size_t W_STRIDE   = (size_t)D_ * D_;    // 1048576

// Softmax scale folded into Q at projection time: 1/sqrt(64) * log2(e)
constexpr float QSCALE = 0.18033688011112042f;

// Scratch (device globals: allocation-free rule)
__device__ float g_cos[S_ * (DH_ / 2)];
__device__ float g_sin[S_ * (DH_ / 2)];
__device__ __nv_bfloat16 g_ah[M_TOT * D_];        // hi split: x, later attention out
__device__ __nv_bfloat16 g_al[M_TOT * D_];        // lo split
__device__ __nv_bfloat16 g_wh[4 * W_STRIDE];      // hi split of wq|wk|wv|wo
__device__ __nv_bfloat16 g_wl[4 * W_STRIDE];      // lo split
__device__ __nv_bfloat16 g_qkh[2 * M_TOT * D_];   // hi split of roped (scaled) q|k
__device__ __nv_bfloat16 g_qkl[2 * M_TOT * D_];   // lo split
__device__ __nv_bfloat16 g_vth[M_TOT * D_];       // V^T hi: [bh][d][s]
__device__ __nv_bfloat16 g_vtl[M_TOT * D_];       // V^T lo

// Pool state for the fused attn+wo kernel (reset by prep each replay)
__device__ int g_pool;
__device__ int g_attn_done[64];

// ---------------------------------------------------------------------------
// helpers
// ---------------------------------------------------------------------------
__device__ __forceinline__ uint32_t smem_to_u32(const void* smem_ptr) {
    uint32_t addr;
    asm("{ .reg .u64 tmp; cvta.to.shared.u64 tmp, %1; cvt.u32.u64 %0, tmp; }"
        : "=r"(addr) : "l"(smem_ptr));
    return addr;
}

__device__ __forceinline__ void cp_async16(uint32_t saddr, const void* gptr) {
    asm volatile("cp.async.cg.shared.global [%0], [%1], 16;"
                 :: "r"(saddr), "l"(gptr) : "memory");
}
__device__ __forceinline__ void cp_commit() {
    asm volatile("cp.async.commit_group;" ::: "memory");
}
template <int N>
__device__ __forceinline__ void cp_wait() {
    asm volatile("cp.async.wait_group %0;" :: "n"(N) : "memory");
}

__device__ __forceinline__ void ldmx4(uint32_t* r, uint32_t addr) {
    asm volatile("ldmatrix.sync.aligned.m8n8.x4.shared.b16 {%0,%1,%2,%3}, [%4];"
                 : "=r"(r[0]), "=r"(r[1]), "=r"(r[2]), "=r"(r[3]) : "r"(addr));
}

__device__ __forceinline__ void mma_bf16(float* c, const uint32_t* a,
                                         uint32_t b0, uint32_t b1) {
    asm volatile(
        "mma.sync.aligned.m16n8k16.row.col.f32.bf16.bf16.f32 "
        "{%0,%1,%2,%3}, {%4,%5,%6,%7}, {%8,%9}, {%0,%1,%2,%3};"
        : "+f"(c[0]), "+f"(c[1]), "+f"(c[2]), "+f"(c[3])
        : "r"(a[0]), "r"(a[1]), "r"(a[2]), "r"(a[3]), "r"(b0), "r"(b1));
}

__device__ __forceinline__ float ex2f(float x) {
    float r; asm("ex2.approx.f32 %0, %1;" : "=f"(r) : "f"(x)); return r;
}

__device__ __forceinline__ void split2pack(float x, float y, uint32_t& h, uint32_t& l) {
    asm("cvt.rn.bf16x2.f32 %0, %1, %2;" : "=r"(h) : "f"(y), "f"(x));
    float fx = __uint_as_float(h << 16);
    float fy = __uint_as_float(h & 0xffff0000u);
    float lx = x - fx, ly = y - fy;
    asm("cvt.rn.bf16x2.f32 %0, %1, %2;" : "=r"(l) : "f"(ly), "f"(lx));
}

__device__ __forceinline__ void red_release(int* p, int v) {
    asm volatile("red.release.gpu.global.add.s32 [%0], %1;" :: "l"(p), "r"(v) : "memory");
}
__device__ __forceinline__ int ld_acquire(int* p) {
    int v;
    asm volatile("ld.acquire.gpu.global.s32 %0, [%1];" : "=r"(v) : "l"(p) : "memory");
    return v;
}

// ---------------------------------------------------------------------------
// Fused prep: counter reset + RoPE table (fp32 trig) + x split + w split
// ---------------------------------------------------------------------------
__global__ void prep_kernel(const float* __restrict__ x,
                            const float* __restrict__ w0, const float* __restrict__ w1,
                            const float* __restrict__ w2, const float* __restrict__ w3)
{
    const int bid = blockIdx.x, tid = threadIdx.x;
    if (bid < 256) {
        if (bid == 0) {
            if (tid == 0) g_pool = 0;
            if (tid < 64) g_attn_done[tid] = 0;
        }
        int idx = bid * 256 + tid;   // 65536
        int s = idx >> 5, i = idx & 31;
        float inv = exp2f(-(float)(2 * i) * (13.28771237954945f / 64.0f));
        float ang = (float)s * inv;
        float sv, cv;
        sincosf(ang, &sv, &cv);
        g_cos[idx] = cv;
        g_sin[idx] = sv;
    } else if (bid < 256 + 2048) {
        int base = (bid - 256) * 1024 + tid;
        float4 v[4];
#pragma unroll
        for (int r = 0; r < 4; r++)
            v[r] = reinterpret_cast<const float4*>(x)[base + r * 256];
#pragma unroll
        for (int r = 0; r < 4; r++) {
            uint32_t h0, l0, h1, l1;
            split2pack(v[r].x, v[r].y, h0, l0);
            split2pack(v[r].z, v[r].w, h1, l1);
            reinterpret_cast<uint2*>(g_ah)[base + r * 256] = make_uint2(h0, h1);
            reinterpret_cast<uint2*>(g_al)[base + r * 256] = make_uint2(l0, l1);
        }
    } else {
        const int n4w = (int)(W_STRIDE / 4);
        int gbase = (bid - 2304) * 1024 + tid;
        int z = gbase / n4w;
        int rbase = gbase - z * n4w;
        const float* src = (z == 0) ? w0 : (z == 1) ? w1 : (z == 2) ? w2 : w3;
        float4 v[4];
#pragma unroll
        for (int r = 0; r < 4; r++)
            v[r] = reinterpret_cast<const float4*>(src)[rbase + r * 256];
#pragma unroll
        for (int r = 0; r < 4; r++) {
            uint32_t h0, l0, h1, l1;
            split2pack(v[r].x, v[r].y, h0, l0);
            split2pack(v[r].z, v[r].w, h1, l1);
            reinterpret_cast<uint2*>(g_wh)[gbase + r * 256] = make_uint2(h0, h1);
            reinterpret_cast<uint2*>(g_wl)[gbase + r * 256] = make_uint2(l0, l1);
        }
    }
}

// ---------------------------------------------------------------------------
// QKV GEMM (R13 kernel, verbatim): z=0 -> RoPE+QSCALE bf16 q; z=1 -> RoPE bf16 k;
// z=2 -> smem-transpose V^T bf16. 3-term emulation, 3-stage single-sync ring.
// ---------------------------------------------------------------------------
constexpr int GEMM_SMEM = 98304;

__global__ void __launch_bounds__(256, 2)
gemm_qkv(const __nv_bfloat16* __restrict__ Ah, const __nv_bfloat16* __restrict__ Al)
{
    extern __shared__ char smem[];
    const uint32_t sb = smem_to_u32(smem);
    const int tid = threadIdx.x, lane = tid & 31, wid = tid >> 5;
    const int z = blockIdx.z;
    const __nv_bfloat16* WhZ = g_wh + (size_t)z * W_STRIDE;
    const __nv_bfloat16* WlZ = g_wl + (size_t)z * W_STRIDE;
    const int m0 = blockIdx.y * 128, n0 = blockIdx.x * 128;
    const int wm = (wid >> 1) * 32, wn = (wid & 1) * 64;

    auto issue_loads = [&](int s, int buf) {
        const int k0 = s * 32;
        uint32_t base = sb + buf * 32768u;
#pragma unroll
        for (int i = 0; i < 2; i++) {
            int idx = tid + 256 * i;
            int row = idx >> 2, ch = idx & 3;
            uint32_t sw = (uint32_t)row * 64 + ((uint32_t)(ch ^ ((row >> 1) & 3)) << 4);
            size_t ga = (size_t)(m0 + row) * 1024 + k0 + ch * 8;
            size_t gb = (size_t)(n0 + row) * 1024 + k0 + ch * 8;
            cp_async16(base + sw,          Ah  + ga);
            cp_async16(base + 8192 + sw,   Al  + ga);
            cp_async16(base + 16384 + sw,  WhZ + gb);
            cp_async16(base + 24576 + sw,  WlZ + gb);
        }
        cp_commit();
    };

    float c[2][8][4];
#pragma unroll
    for (int i = 0; i < 2; i++)
#pragma unroll
        for (int j = 0; j < 8; j++)
#pragma unroll
            for (int q = 0; q < 4; q++) c[i][j][q] = 0.f;

    const int mrowA0 = wm + ((lane >> 3) & 1) * 8 + (lane & 7);
    const int kcA    = (lane >> 4) & 1;
    const int nrowB0 = wn + ((lane >> 4) & 1) * 8 + (lane & 7);
    const int kcB    = (lane >> 3) & 1;

    issue_loads(0, 0);
    issue_loads(1, 1);

    for (int s = 0; s < 32; s++) {
        const int buf = s % 3;
        if (s + 1 < 32) cp_wait<1>(); else cp_wait<0>();
        __syncthreads();
        if (s + 2 < 32) issue_loads(s + 2, (s + 2) % 3);

        const uint32_t abase = sb + buf * 32768u;
        const uint32_t bbase = abase + 16384u;
#pragma unroll
        for (int kc2 = 0; kc2 < 2; kc2++) {
            uint32_t ah[2][4], al[2][4];
#pragma unroll
            for (int i = 0; i < 2; i++) {
                int mr = mrowA0 + 16 * i;
                int unit = (kc2 << 1) | kcA;
                uint32_t addr = abase + mr * 64 +
                    ((uint32_t)(unit ^ ((mr >> 1) & 3)) << 4);
                ldmx4(ah[i], addr);
                ldmx4(al[i], addr + 8192);
            }
#pragma unroll
            for (int j = 0; j < 4; j++) {
                int nr = nrowB0 + 16 * j;
                int unit = (kc2 << 1) | kcB;
                uint32_t baddr = bbase + nr * 64 +
                    ((uint32_t)(unit ^ ((nr >> 1) & 3)) << 4);
                uint32_t bh[4], bl[4];
                ldmx4(bh, baddr);
                ldmx4(bl, baddr + 8192);
#pragma unroll
                for (int i = 0; i < 2; i++) {
                    mma_bf16(c[i][2 * j],     ah[i], bh[0], bh[1]);
                    mma_bf16(c[i][2 * j + 1], ah[i], bh[2], bh[3]);
                    mma_bf16(c[i][2 * j],     al[i], bh[0], bh[1]);
                    mma_bf16(c[i][2 * j + 1], al[i], bh[2], bh[3]);
                    mma_bf16(c[i][2 * j],     ah[i], bl[0], bl[1]);
                    mma_bf16(c[i][2 * j + 1], ah[i], bl[2], bl[3]);
                }
            }
        }
    }

    const int g = lane >> 2, tig = lane & 3;

    if (z < 2) {
        const float qs = (z == 0) ? QSCALE : 1.0f;
        __nv_bfloat16* DhZ = g_qkh + (size_t)z * QKV_STRIDE;
        __nv_bfloat16* DlZ = g_qkl + (size_t)z * QKV_STRIDE;
#pragma unroll
        for (int i = 0; i < 2; i++) {
            int mrow = m0 + wm + 16 * i + g;
            int s0 = mrow & 2047, s1 = (mrow + 8) & 2047;
#pragma unroll
            for (int nt = 0; nt < 8; nt++) {
                int col = n0 + wn + nt * 8 + tig * 2;
                int fi = (col & 63) >> 1;
                float cv0 = g_cos[s0 * 32 + fi], sv0 = g_sin[s0 * 32 + fi];
                float cv1 = g_cos[s1 * 32 + fi], sv1 = g_sin[s1 * 32 + fi];
                float r0 = (c[i][nt][0] * cv0 - c[i][nt][1] * sv0) * qs;
                float r1 = (c[i][nt][0] * sv0 + c[i][nt][1] * cv0) * qs;
                float r2 = (c[i][nt][2] * cv1 - c[i][nt][3] * sv1) * qs;
                float r3 = (c[i][nt][2] * sv1 + c[i][nt][3] * cv1) * qs;
                uint32_t h, l;
                size_t idx0 = (size_t)mrow * 1024 + col;
                split2pack(r0, r1, h, l);
                *reinterpret_cast<uint32_t*>(DhZ + idx0) = h;
                *reinterpret_cast<uint32_t*>(DlZ + idx0) = l;
                size_t idx1 = idx0 + (size_t)8 * 1024;
                split2pack(r2, r3, h, l);
                *reinterpret_cast<uint32_t*>(DhZ + idx1) = h;
                *reinterpret_cast<uint32_t*>(DlZ + idx1) = l;
            }
        }
    } else {
        __syncthreads();
        float* ts = reinterpret_cast<float*>(smem);   // [128][132]
#pragma unroll
        for (int i = 0; i < 2; i++) {
            int r0 = wm + 16 * i + g;
#pragma unroll
            for (int nt = 0; nt < 8; nt++) {
                int cc = wn + nt * 8 + tig * 2;
                *reinterpret_cast<float2*>(&ts[r0 * 132 + cc]) =
                    make_float2(c[i][nt][0], c[i][nt][1]);
                *reinterpret_cast<float2*>(&ts[(r0 + 8) * 132 + cc]) =
                    make_float2(c[i][nt][2], c[i][nt][3]);
            }
        }
        __syncthreads();
        const int col = tid & 127;
        const int shalf = (tid >> 7) * 64;
        const int b = m0 >> 11;
        const int sg = (m0 & 2047) + shalf;
        const int hd = (n0 + col) >> 6, d = (n0 + col) & 63;
        size_t obase = ((size_t)((b * 16 + hd) * 64 + d)) * 2048 + sg;
        __nv_bfloat16* vh = g_vth + obase;
        __nv_bfloat16* vl = g_vtl + obase;
#pragma unroll
        for (int t8 = 0; t8 < 8; t8++) {
            uint32_t hb[4], lb[4];
#pragma unroll
            for (int p = 0; p < 4; p++) {
                int sr = shalf + t8 * 8 + 2 * p;
                float v0 = ts[sr * 132 + col];
                float v1 = ts[(sr + 1) * 132 + col];
                split2pack(v0, v1, hb[p], lb[p]);
            }
            *reinterpret_cast<uint4*>(vh + t8 * 8) = make_uint4(hb[0], hb[1], hb[2], hb[3]);
            *reinterpret_cast<uint4*>(vl + t8 * 8) = make_uint4(lb[0], lb[1], lb[2], lb[3]);
        }
    }
}

// ---------------------------------------------------------------------------
// Attention tile body (R13 arithmetic, verbatim). Single call site.
// ---------------------------------------------------------------------------
constexpr uint32_t QH_O = 0, QL_O = 16384, KV_O = 32768;

__device__ __forceinline__ void attn_tile(char* smem, int qt, int bh)
{
    const uint32_t sb = smem_to_u32(smem);
    const int tid = threadIdx.x, lane = tid & 31, w = tid >> 5;
    const int b = bh >> 4, h = bh & 15;
    const int q0 = qt * 128;
    const int njk = 2 * qt + 2;

    auto issue_kv = [&](int jk, int buf) {
        uint32_t base = sb + KV_O + buf * 32768u;
#pragma unroll
        for (int i = 0; i < 2; i++) {
            int idx = tid + 256 * i;
            int r = idx >> 3, ch = idx & 7;
            uint32_t sw = r * 128 + ((ch ^ (r & 7)) << 4);
            size_t gk = QKV_STRIDE + (size_t)(b * 2048 + jk * 64 + r) * 1024 + h * 64 + ch * 8;
            cp_async16(base + sw,         g_qkh + gk);
            cp_async16(base + 8192 + sw,  g_qkl + gk);
            size_t gv = ((size_t)bh * 64 + r) * 2048 + jk * 64 + ch * 8;
            cp_async16(base + 16384 + sw, g_vth + gv);
            cp_async16(base + 24576 + sw, g_vtl + gv);
        }
        cp_commit();
    };

#pragma unroll
    for (int i = 0; i < 4; i++) {
        int idx = tid + 256 * i;
        int r = idx >> 3, ch = idx & 7;
        size_t gq = (size_t)(b * 2048 + q0 + r) * 1024 + h * 64 + ch * 8;
        uint32_t sw = r * 128 + ((ch ^ (r & 7)) << 4);
        cp_async16(sb + QH_O + sw, g_qkh + gq);
        cp_async16(sb + QL_O + sw, g_qkl + gq);
    }
    cp_commit();
    issue_kv(0, 0);

    float o[8][4];
#pragma unroll
    for (int nt = 0; nt < 8; nt++)
#pragma unroll
        for (int q = 0; q < 4; q++) o[nt][q] = 0.f;
    float m0 = -1e30f, m1 = -1e30f, l0 = 0.f, l1 = 0.f;

    const int g_  = lane >> 2, tig = lane & 3;
    const int mrA = w * 16 + ((lane >> 3) & 1) * 8 + (lane & 7);
    const int kcA = (lane >> 4) & 1;
    const int nrB = ((lane >> 4) & 1) * 8 + (lane & 7);
    const int kcB = (lane >> 3) & 1;
    const int row0 = q0 + w * 16 + g_;
    const int wrow_max = q0 + w * 16 + 15;

    for (int jk = 0; jk < njk; jk++) {
        const int buf = jk & 1;
        cp_wait<0>();
        __syncthreads();
        if (jk + 1 < njk) issue_kv(jk + 1, buf ^ 1);

        if (jk * 64 > wrow_max) continue;   // exact no-op: skip

        const uint32_t kbase = sb + KV_O + buf * 32768u;
        const uint32_t vbase = kbase + 16384u;

        float c[8][4];
#pragma unroll
        for (int nt = 0; nt < 8; nt++)
#pragma unroll
            for (int q = 0; q < 4; q++) c[nt][q] = 0.f;

#pragma unroll
        for (int k16 = 0; k16 < 4; k16++) {
            uint32_t ah[4], al[4];
            uint32_t aaddr = sb + QH_O + mrA * 128 +
                ((((k16 << 1) | kcA) ^ (mrA & 7)) << 4);
            ldmx4(ah, aaddr);
            ldmx4(al, aaddr + (QL_O - QH_O));
#pragma unroll
            for (int j = 0; j < 4; j++) {
                int nr = 16 * j + nrB;
                uint32_t baddr = kbase + nr * 128 +
                    ((((k16 << 1) | kcB) ^ (nr & 7)) << 4);
                uint32_t bhh[4], bll[4];
                ldmx4(bhh, baddr);
                ldmx4(bll, baddr + 8192);
                mma_bf16(c[2 * j],     ah, bhh[0], bhh[1]);
                mma_bf16(c[2 * j + 1], ah, bhh[2], bhh[3]);
                mma_bf16(c[2 * j],     al, bhh[0], bhh[1]);
                mma_bf16(c[2 * j + 1], al, bhh[2], bhh[3]);
                mma_bf16(c[2 * j],     ah, bll[0], bll[1]);
                mma_bf16(c[2 * j + 1], ah, bll[2], bll[3]);
            }
        }

        if (jk >= 2 * qt) {
#pragma unroll
            for (int nt = 0; nt < 8; nt++) {
                int colg = jk * 64 + 8 * nt + 2 * tig;
                if (colg     > row0)     c[nt][0] = -1e30f;
                if (colg + 1 > row0)     c[nt][1] = -1e30f;
                if (colg     > row0 + 8) c[nt][2] = -1e30f;
                if (colg + 1 > row0 + 8) c[nt][3] = -1e30f;
            }
        }

        float rm0 = -1e30f, rm1 = -1e30f;
#pragma unroll
        for (int nt = 0; nt < 8; nt++) {
            rm0 = fmaxf(rm0, fmaxf(c[nt][0], c[nt][1]));
            rm1 = fmaxf(rm1, fmaxf(c[nt][2], c[nt][3]));
        }
        rm0 = fmaxf(rm0, __shfl_xor_sync(0xffffffffu, rm0, 1));
        rm0 = fmaxf(rm0, __shfl_xor_sync(0xffffffffu, rm0, 2));
        rm1 = fmaxf(rm1, __shfl_xor_sync(0xffffffffu, rm1, 1));
        rm1 = fmaxf(rm1, __shfl_xor_sync(0xffffffffu, rm1, 2));

        float mn0 = fmaxf(m0, rm0), mn1 = fmaxf(m1, rm1);
        float a0 = ex2f(m0 - mn0), a1 = ex2f(m1 - mn1);
        m0 = mn0; m1 = mn1;

        float rs0 = 0.f, rs1 = 0.f;
#pragma unroll
        for (int nt = 0; nt < 8; nt++) {
            c[nt][0] = ex2f(c[nt][0] - mn0);
            c[nt][1] = ex2f(c[nt][1] - mn0);
            c[nt][2] = ex2f(c[nt][2] - mn1);
            c[nt][3] = ex2f(c[nt][3] - mn1);
            rs0 += c[nt][0] + c[nt][1];
            rs1 += c[nt][2] + c[nt][3];
        }
        rs0 += __shfl_xor_sync(0xffffffffu, rs0, 1);
        rs0 += __shfl_xor_sync(0xffffffffu, rs0, 2);
        rs1 += __shfl_xor_sync(0xffffffffu, rs1, 1);
        rs1 += __shfl_xor_sync(0xffffffffu, rs1, 2);
        l0 = l0 * a0 + rs0;
        l1 = l1 * a1 + rs1;
#pragma unroll
        for (int nt = 0; nt < 8; nt++) {
            o[nt][0] *= a0; o[nt][1] *= a0;
            o[nt][2] *= a1; o[nt][3] *= a1;
        }

#pragma unroll
        for (int k16 = 0; k16 < 4; k16++) {
            uint32_t aph[4], apl[4];
            split2pack(c[2 * k16][0],     c[2 * k16][1],     aph[0], apl[0]);
            split2pack(c[2 * k16][2],     c[2 * k16][3],     aph[1], apl[1]);
            split2pack(c[2 * k16 + 1][0], c[2 * k16 + 1][1], aph[2], apl[2]);
            split2pack(c[2 * k16 + 1][2], c[2 * k16 + 1][3], aph[3], apl[3]);
#pragma unroll
            for (int j = 0; j < 4; j++) {
                int nr = 16 * j + nrB;
                uint32_t baddr = vbase + nr * 128 +
                    ((((k16 << 1) | kcB) ^ (nr & 7)) << 4);
                uint32_t vhh[4], vll[4];
                ldmx4(vhh, baddr);
                ldmx4(vll, baddr + 8192);
                mma_bf16(o[2 * j],     aph, vhh[0], vhh[1]);
                mma_bf16(o[2 * j + 1], aph, vhh[2], vhh[3]);
                mma_bf16(o[2 * j],     apl, vhh[0], vhh[1]);
                mma_bf16(o[2 * j + 1], apl, vhh[2], vhh[3]);
                mma_bf16(o[2 * j],     aph, vll[0], vll[1]);
                mma_bf16(o[2 * j + 1], aph, vll[2], vll[3]);
            }
        }
    }

    float inv0 = 1.0f / l0, inv1 = 1.0f / l1;
    size_t base0 = (size_t)(b * 2048 + row0) * 1024 + h * 64 + 2 * tig;
    size_t base1 = base0 + (size_t)8 * 1024;
#pragma unroll
    for (int nt = 0; nt < 8; nt++) {
        uint32_t hh, ll;
        split2pack(o[nt][0] * inv0, o[nt][1] * inv0, hh, ll);
        *reinterpret_cast<uint32_t*>(g_ah + base0 + 8 * nt) = hh;
        *reinterpret_cast<uint32_t*>(g_al + base0 + 8 * nt) = ll;
        split2pack(o[nt][2] * inv1, o[nt][3] * inv1, hh, ll);
        *reinterpret_cast<uint32_t*>(g_ah + base1 + 8 * nt) = hh;
        *reinterpret_cast<uint32_t*>(g_al + base1 + 8 * nt) = ll;
    }
}

// ---------------------------------------------------------------------------
// wo GEMM tile body (R13 arithmetic, fp32 epilogue). Single call site.
// ---------------------------------------------------------------------------
__device__ __forceinline__ void wo_tile(char* smem, int m0, int n0,
                                        float* __restrict__ out)
{
    const uint32_t sb = smem_to_u32(smem);
    const int tid = threadIdx.x, lane = tid & 31, wid = tid >> 5;
    const __nv_bfloat16* WhZ = g_wh + 3 * W_STRIDE;
    const __nv_bfloat16* WlZ = g_wl + 3 * W_STRIDE;
    const int wm = (wid >> 1) * 32, wn = (wid & 1) * 64;

    auto issue_loads = [&](int s, int buf) {
        const int k0 = s * 32;
        uint32_t base = sb + buf * 32768u;
#pragma unroll
        for (int i = 0; i < 2; i++) {
            int idx = tid + 256 * i;
            int row = idx >> 2, ch = idx & 3;
            uint32_t sw = (uint32_t)row * 64 + ((uint32_t)(ch ^ ((row >> 1) & 3)) << 4);
            size_t ga = (size_t)(m0 + row) * 1024 + k0 + ch * 8;
            size_t gb = (size_t)(n0 + row) * 1024 + k0 + ch * 8;
            cp_async16(base + sw,          g_ah + ga);
            cp_async16(base + 8192 + sw,   g_al + ga);
            cp_async16(base + 16384 + sw,  WhZ  + gb);
            cp_async16(base + 24576 + sw,  WlZ  + gb);
        }
        cp_commit();
    };

    float c[2][8][4];
#pragma unroll
    for (int i = 0; i < 2; i++)
#pragma unroll
        for (int j = 0; j < 8; j++)
#pragma unroll
            for (int q = 0; q < 4; q++) c[i][j][q] = 0.f;

    const int mrowA0 = wm + ((lane >> 3) & 1) * 8 + (lane & 7);
    const int kcA    = (lane >> 4) & 1;
    const int nrowB0 = wn + ((lane >> 4) & 1) * 8 + (lane & 7);
    const int kcB    = (lane >> 3) & 1;

    issue_loads(0, 0);
    issue_loads(1, 1);

    for (int s = 0; s < 32; s++) {
        const int buf = s % 3;
        if (s + 1 < 32) cp_wait<1>(); else cp_wait<0>();
        __syncthreads();
        if (s + 2 < 32) issue_loads(s + 2, (s + 2) % 3);

        const uint32_t abase = sb + buf * 32768u;
        const uint32_t bbase = abase + 16384u;
#pragma unroll
        for (int kc2 = 0; kc2 < 2; kc2++) {
            uint32_t ah[2][4], al[2][4];
#pragma unroll
            for (int i = 0; i < 2; i++) {
                int mr = mrowA0 + 16 * i;
                int unit = (kc2 << 1) | kcA;
                uint32_t addr = abase + mr * 64 +
                    ((uint32_t)(unit ^ ((mr >> 1) & 3)) << 4);
                ldmx4(ah[i], addr);
                ldmx4(al[i], addr + 8192);
            }
#pragma unroll
            for (int j = 0; j < 4; j++) {
                int nr = nrowB0 + 16 * j;
                int unit = (kc2 << 1) | kcB;
                uint32_t baddr = bbase + nr * 64 +
                    ((uint32_t)(unit ^ ((nr >> 1) & 3)) << 4);
                uint32_t bh[4], bl[4];
                ldmx4(bh, baddr);
                ldmx4(bl, baddr + 8192);
#pragma unroll
                for (int i = 0; i < 2; i++) {
                    mma_bf16(c[i][2 * j],     ah[i], bh[0], bh[1]);
                    mma_bf16(c[i][2 * j + 1], ah[i], bh[2], bh[3]);
                    mma_bf16(c[i][2 * j],     al[i], bh[0], bh[1]);
                    mma_bf16(c[i][2 * j + 1], al[i], bh[2], bh[3]);
                    mma_bf16(c[i][2 * j],     ah[i], bl[0], bl[1]);
                    mma_bf16(c[i][2 * j + 1], ah[i], bl[2], bl[3]);
                }
            }
        }
    }

    const int g = lane >> 2, tig = lane & 3;
#pragma unroll
    for (int i = 0; i < 2; i++) {
        int mrow = m0 + wm + 16 * i + g;
#pragma unroll
        for (int nt = 0; nt < 8; nt++) {
            int col = n0 + wn + nt * 8 + tig * 2;
            float* p = out + (size_t)mrow * 1024 + col;
            *reinterpret_cast<float2*>(p) = make_float2(c[i][nt][0], c[i][nt][1]);
            *reinterpret_cast<float2*>(p + 8 * 1024) = make_float2(c[i][nt][2], c[i][nt][3]);
        }
    }
}

// ---------------------------------------------------------------------------
// Persistent attn+wo kernel. Pool:
//   [0,1024)    : attention tiles, qt descending (heavy first)
//   [1024,1536) : wo tiles, qt descending; gated on attn_done[(b,qt)]==16
// wo tiles backfill attention's ragged tail. QKV completed by prior launch.
// ---------------------------------------------------------------------------
constexpr int AW_SMEM = 98304;

__global__ void __launch_bounds__(256, 2)
attn_wo_kernel(float* __restrict__ out)
{
    extern __shared__ char smem[];
    __shared__ int s_idx;
    const int tid = threadIdx.x;

    for (;;) {
        __syncthreads();                      // prior tile fully done (smem reuse)
        if (tid == 0) s_idx = atomicAdd(&g_pool, 1);
        __syncthreads();
        const int idx = s_idx;
        if (idx >= 1536) return;

        if (idx < 1024) {
            // attention tile: qt descending, then bh
            int qt = 15 - (idx >> 6);
            int bh = idx & 63;
            attn_tile(smem, qt, bh);
            __threadfence();
            __syncthreads();
            if (tid == 0) red_release(&g_attn_done[(bh >> 4) * 16 + qt], 1);
        } else {
            // wo tile: qt descending; needs all 16 heads of its (batch, qt)
            int a = idx - 1024;                 // 0..511
            int qt = 15 - (a >> 5);
            int e = a & 31;
            int batch = e >> 3, nt = e & 7;
            if (tid == 0) {
                while (ld_acquire(&g_attn_done[batch * 16 + qt]) < 16) __nanosleep(256);
            }
            __syncthreads();
            wo_tile(smem, (batch * 16 + qt) * 128, nt * 128, out);
        }
    }
}

// ---------------------------------------------------------------------------
extern "C" void kernel_launch(void* const* d_in, const int* in_sizes, int n_in,
                              void* d_out, int out_size)
{
    (void)in_sizes; (void)n_in; (void)out_size;
    const float* x  = (const float*)d_in[0];
    const float* wq = (const float*)d_in[1];
    const float* wk = (const float*)d_in[2];
    const float* wv = (const float*)d_in[3];
    const float* wo = (const float*)d_in[4];
    float* out = (float*)d_out;

    __nv_bfloat16 *pah, *pal;
    cudaGetSymbolAddress((void**)&pah, g_ah);
    cudaGetSymbolAddress((void**)&pal, g_al);

    cudaFuncSetAttribute(gemm_qkv, cudaFuncAttributeMaxDynamicSharedMemorySize, GEMM_SMEM);
    cudaFuncSetAttribute(attn_wo_kernel, cudaFuncAttributeMaxDynamicSharedMemorySize, AW_SMEM);

    int nsm = 148;
    cudaDeviceGetAttribute(&nsm, cudaDevAttrMultiProcessorCount, 0);

    // Prep: counters + rope table + x/w splits
    prep_kernel<<<256 + 2048 + 1024, 256>>>(x, wq, wk, wv, wo);

    // QKV projection (clean launch; no harvestable overlap across this boundary)
    gemm_qkv<<<dim3(8, 64, 3), 256, GEMM_SMEM>>>(pah, pal);

    // Attention + wo in one persistent launch: wo backfills the attention tail
    attn_wo_kernel<<<2 * nsm, 256, AW_SMEM>>>(out);
}

// round 17
// speedup vs baseline: 1.4823x; 1.0421x over previous
#include <cuda_runtime.h>
#include <cuda_bf16.h>
#include <cstdint>

// ---------------------------------------------------------------------------
// Problem constants
// ---------------------------------------------------------------------------
constexpr int B_  = 4;
constexpr int S_  = 2048;
constexpr int D_  = 1024;
constexpr int H_  = 16;
constexpr int DH_ = 64;
constexpr int M_TOT = B_ * S_;                    // 8192
constexpr size_t QKV_STRIDE = (size_t)M_TOT * D_; // 8388608
constexpr size_t W_STRIDE   = (size_t)D_ * D_;    // 1048576

// Softmax scale folded into Q at projection time: 1/sqrt(64) * log2(e)
constexpr float QSCALE = 0.18033688011112042f;

// Scratch (device globals: allocation-free rule)
__device__ float g_cos[S_ * (DH_ / 2)];
__device__ float g_sin[S_ * (DH_ / 2)];
__device__ __nv_bfloat16 g_ah[M_TOT * D_];        // hi split: x, later attention out
__device__ __nv_bfloat16 g_al[M_TOT * D_];        // lo split
__device__ __nv_bfloat16 g_wh[4 * W_STRIDE];      // hi split of wq|wk|wv|wo
__device__ __nv_bfloat16 g_wl[4 * W_STRIDE];      // lo split
__device__ __nv_bfloat16 g_qkh[2 * M_TOT * D_];   // hi split of roped (scaled) q|k
__device__ __nv_bfloat16 g_qkl[2 * M_TOT * D_];   // lo split
__device__ __nv_bfloat16 g_vth[M_TOT * D_];       // V^T hi: [bh][d][s]
__device__ __nv_bfloat16 g_vtl[M_TOT * D_];       // V^T lo

// ---------------------------------------------------------------------------
// helpers
// ---------------------------------------------------------------------------
__device__ __forceinline__ uint32_t smem_to_u32(const void* smem_ptr) {
    uint32_t addr;
    asm("{ .reg .u64 tmp; cvta.to.shared.u64 tmp, %1; cvt.u32.u64 %0, tmp; }"
        : "=r"(addr) : "l"(smem_ptr));
    return addr;
}

__device__ __forceinline__ void cp_async16(uint32_t saddr, const void* gptr) {
    asm volatile("cp.async.cg.shared.global [%0], [%1], 16;"
                 :: "r"(saddr), "l"(gptr) : "memory");
}
__device__ __forceinline__ void cp_commit() {
    asm volatile("cp.async.commit_group;" ::: "memory");
}
template <int N>
__device__ __forceinline__ void cp_wait() {
    asm volatile("cp.async.wait_group %0;" :: "n"(N) : "memory");
}

__device__ __forceinline__ void ldmx4(uint32_t* r, uint32_t addr) {
    asm volatile("ldmatrix.sync.aligned.m8n8.x4.shared.b16 {%0,%1,%2,%3}, [%4];"
                 : "=r"(r[0]), "=r"(r[1]), "=r"(r[2]), "=r"(r[3]) : "r"(addr));
}

__device__ __forceinline__ void mma_bf16(float* c, const uint32_t* a,
                                         uint32_t b0, uint32_t b1) {
    asm volatile(
        "mma.sync.aligned.m16n8k16.row.col.f32.bf16.bf16.f32 "
        "{%0,%1,%2,%3}, {%4,%5,%6,%7}, {%8,%9}, {%0,%1,%2,%3};"
        : "+f"(c[0]), "+f"(c[1]), "+f"(c[2]), "+f"(c[3])
        : "r"(a[0]), "r"(a[1]), "r"(a[2]), "r"(a[3]), "r"(b0), "r"(b1));
}

// exp2 via MUFU (single instruction)
__device__ __forceinline__ float ex2f(float x) {
    float r; asm("ex2.approx.f32 %0, %1;" : "=f"(r) : "f"(x)); return r;
}

// Split 2 floats -> packed bf16 hi pair + packed bf16 lo pair.
__device__ __forceinline__ void split2pack(float x, float y, uint32_t& h, uint32_t& l) {
    asm("cvt.rn.bf16x2.f32 %0, %1, %2;" : "=r"(h) : "f"(y), "f"(x));  // hi=y, lo=x
    float fx = __uint_as_float(h << 16);
    float fy = __uint_as_float(h & 0xffff0000u);
    float lx = x - fx, ly = y - fy;
    asm("cvt.rn.bf16x2.f32 %0, %1, %2;" : "=r"(l) : "f"(ly), "f"(lx));
}

// ---------------------------------------------------------------------------
// Fused prep:
//   blocks [0,256)        : RoPE table (fp32 trig — matches the reference's
//                           own fp32 angle computation; no DP transcendentals)
//   blocks [256,2304)     : x split (4 float4/thread)
//   blocks [2304,3328)    : w split (4 float4/thread)
// ---------------------------------------------------------------------------
__global__ void prep_kernel(const float* __restrict__ x,
                            const float* __restrict__ w0, const float* __restrict__ w1,
                            const float* __restrict__ w2, const float* __restrict__ w3,
                            __nv_bfloat16* __restrict__ ah, __nv_bfloat16* __restrict__ al,
                            __nv_bfloat16* __restrict__ wh, __nv_bfloat16* __restrict__ wl)
{
    const int bid = blockIdx.x, tid = threadIdx.x;
    if (bid < 256) {
        int idx = bid * 256 + tid;   // 65536
        int s = idx >> 5, i = idx & 31;
        float inv = exp2f(-(float)(2 * i) * (13.28771237954945f / 64.0f));
        float ang = (float)s * inv;   // fp32 angle, exactly like the reference
        float sv, cv;
        sincosf(ang, &sv, &cv);
        g_cos[idx] = cv;
        g_sin[idx] = sv;
    } else if (bid < 256 + 2048) {
        // x split: 2097152 float4, 4 per thread
        int base = (bid - 256) * 1024 + tid;
        float4 v[4];
#pragma unroll
        for (int r = 0; r < 4; r++)
            v[r] = reinterpret_cast<const float4*>(x)[base + r * 256];
#pragma unroll
        for (int r = 0; r < 4; r++) {
            uint32_t h0, l0, h1, l1;
            split2pack(v[r].x, v[r].y, h0, l0);
            split2pack(v[r].z, v[r].w, h1, l1);
            reinterpret_cast<uint2*>(ah)[base + r * 256] = make_uint2(h0, h1);
            reinterpret_cast<uint2*>(al)[base + r * 256] = make_uint2(l0, l1);
        }
    } else {
        const int n4w = (int)(W_STRIDE / 4);          // 262144
        int gbase = (bid - 2304) * 1024 + tid;
        int z = gbase / n4w;                          // uniform per block
        int rbase = gbase - z * n4w;
        const float* src = (z == 0) ? w0 : (z == 1) ? w1 : (z == 2) ? w2 : w3;
        float4 v[4];
#pragma unroll
        for (int r = 0; r < 4; r++)
            v[r] = reinterpret_cast<const float4*>(src)[rbase + r * 256];
#pragma unroll
        for (int r = 0; r < 4; r++) {
            uint32_t h0, l0, h1, l1;
            split2pack(v[r].x, v[r].y, h0, l0);
            split2pack(v[r].z, v[r].w, h1, l1);
            reinterpret_cast<uint2*>(wh)[gbase + r * 256] = make_uint2(h0, h1);
            reinterpret_cast<uint2*>(wl)[gbase + r * 256] = make_uint2(l0, l1);
        }
    }
}

// ---------------------------------------------------------------------------
// bf16 mma.sync GEMM, fused 3-term fp32 emulation, single-sync 3-stage ring.
// BM=BN=128 (measured-best schedule).
// fused=1 (QKV): z=0 -> RoPE+QSCALE -> bf16 hi/lo; z=1 -> RoPE -> bf16 hi/lo;
//                z=2 -> smem-transpose -> V^T bf16 hi/lo.
// fused=0: fp32 epilogue to Df.
// ---------------------------------------------------------------------------
constexpr int GEMM_SMEM = 98304;   // 3 stages * 32KB; also fits 128x132 f32 staging

__global__ void __launch_bounds__(256, 2)
gemm_bf3(const __nv_bfloat16* __restrict__ Ah, const __nv_bfloat16* __restrict__ Al,
         const __nv_bfloat16* __restrict__ Wh, const __nv_bfloat16* __restrict__ Wl,
         float* __restrict__ Df,
         __nv_bfloat16* __restrict__ Dh, __nv_bfloat16* __restrict__ Dl,
         __nv_bfloat16* __restrict__ Vh, __nv_bfloat16* __restrict__ Vl,
         int fused)
{
    extern __shared__ char smem[];
    const uint32_t sb = smem_to_u32(smem);
    const int tid = threadIdx.x, lane = tid & 31, wid = tid >> 5;
    const int z = blockIdx.z;
    const __nv_bfloat16* WhZ = Wh + (size_t)z * W_STRIDE;
    const __nv_bfloat16* WlZ = Wl + (size_t)z * W_STRIDE;
    const int m0 = blockIdx.y * 128, n0 = blockIdx.x * 128;
    const int wm = (wid >> 1) * 32, wn = (wid & 1) * 64;

    auto issue_loads = [&](int s, int buf) {
        const int k0 = s * 32;
        uint32_t base = sb + buf * 32768u;
#pragma unroll
        for (int i = 0; i < 2; i++) {
            int idx = tid + 256 * i;
            int row = idx >> 2, ch = idx & 3;
            uint32_t sw = (uint32_t)row * 64 + ((uint32_t)(ch ^ ((row >> 1) & 3)) << 4);
            size_t ga = (size_t)(m0 + row) * 1024 + k0 + ch * 8;
            size_t gb = (size_t)(n0 + row) * 1024 + k0 + ch * 8;
            cp_async16(base + sw,          Ah  + ga);
            cp_async16(base + 8192 + sw,   Al  + ga);
            cp_async16(base + 16384 + sw,  WhZ + gb);
            cp_async16(base + 24576 + sw,  WlZ + gb);
        }
        cp_commit();
    };

    float c[2][8][4];
#pragma unroll
    for (int i = 0; i < 2; i++)
#pragma unroll
        for (int j = 0; j < 8; j++)
#pragma unroll
            for (int q = 0; q < 4; q++) c[i][j][q] = 0.f;

    const int mrowA0 = wm + ((lane >> 3) & 1) * 8 + (lane & 7);
    const int kcA    = (lane >> 4) & 1;
    const int nrowB0 = wn + ((lane >> 4) & 1) * 8 + (lane & 7);
    const int kcB    = (lane >> 3) & 1;

    issue_loads(0, 0);
    issue_loads(1, 1);

    for (int s = 0; s < 32; s++) {
        const int buf = s % 3;
        if (s + 1 < 32) cp_wait<1>(); else cp_wait<0>();
        __syncthreads();
        if (s + 2 < 32) issue_loads(s + 2, (s + 2) % 3);

        const uint32_t abase = sb + buf * 32768u;
        const uint32_t bbase = abase + 16384u;
#pragma unroll
        for (int kc2 = 0; kc2 < 2; kc2++) {
            uint32_t ah[2][4], al[2][4];
#pragma unroll
            for (int i = 0; i < 2; i++) {
                int mr = mrowA0 + 16 * i;
                int unit = (kc2 << 1) | kcA;
                uint32_t addr = abase + mr * 64 +
                    ((uint32_t)(unit ^ ((mr >> 1) & 3)) << 4);
                ldmx4(ah[i], addr);
                ldmx4(al[i], addr + 8192);
            }
#pragma unroll
            for (int j = 0; j < 4; j++) {
                int nr = nrowB0 + 16 * j;
                int unit = (kc2 << 1) | kcB;
                uint32_t baddr = bbase + nr * 64 +
                    ((uint32_t)(unit ^ ((nr >> 1) & 3)) << 4);
                uint32_t bh[4], bl[4];
                ldmx4(bh, baddr);
                ldmx4(bl, baddr + 8192);
#pragma unroll
                for (int i = 0; i < 2; i++) {
                    mma_bf16(c[i][2 * j],     ah[i], bh[0], bh[1]);
                    mma_bf16(c[i][2 * j + 1], ah[i], bh[2], bh[3]);
                    mma_bf16(c[i][2 * j],     al[i], bh[0], bh[1]);
                    mma_bf16(c[i][2 * j + 1], al[i], bh[2], bh[3]);
                    mma_bf16(c[i][2 * j],     ah[i], bl[0], bl[1]);
                    mma_bf16(c[i][2 * j + 1], ah[i], bl[2], bl[3]);
                }
            }
        }
    }

    const int g = lane >> 2, tig = lane & 3;

    if (fused && z < 2) {
        // RoPE (+ QSCALE for q) + bf16 hi/lo epilogue
        const float qs = (z == 0) ? QSCALE : 1.0f;
        __nv_bfloat16* DhZ = Dh + (size_t)z * QKV_STRIDE;
        __nv_bfloat16* DlZ = Dl + (size_t)z * QKV_STRIDE;
#pragma unroll
        for (int i = 0; i < 2; i++) {
            int mrow = m0 + wm + 16 * i + g;
            int s0 = mrow & 2047, s1 = (mrow + 8) & 2047;
#pragma unroll
            for (int nt = 0; nt < 8; nt++) {
                int col = n0 + wn + nt * 8 + tig * 2;
                int fi = (col & 63) >> 1;
                float cv0 = g_cos[s0 * 32 + fi], sv0 = g_sin[s0 * 32 + fi];
                float cv1 = g_cos[s1 * 32 + fi], sv1 = g_sin[s1 * 32 + fi];
                float r0 = (c[i][nt][0] * cv0 - c[i][nt][1] * sv0) * qs;
                float r1 = (c[i][nt][0] * sv0 + c[i][nt][1] * cv0) * qs;
                float r2 = (c[i][nt][2] * cv1 - c[i][nt][3] * sv1) * qs;
                float r3 = (c[i][nt][2] * sv1 + c[i][nt][3] * cv1) * qs;
                uint32_t h, l;
                size_t idx0 = (size_t)mrow * 1024 + col;
                split2pack(r0, r1, h, l);
                *reinterpret_cast<uint32_t*>(DhZ + idx0) = h;
                *reinterpret_cast<uint32_t*>(DlZ + idx0) = l;
                size_t idx1 = idx0 + (size_t)8 * 1024;
                split2pack(r2, r3, h, l);
                *reinterpret_cast<uint32_t*>(DhZ + idx1) = h;
                *reinterpret_cast<uint32_t*>(DlZ + idx1) = l;
            }
        }
    } else if (fused) {
        // z == 2: V tile -> transpose via smem -> V^T bf16 hi/lo [bh][d][s]
        __syncthreads();                       // mainloop smem reads done
        float* ts = reinterpret_cast<float*>(smem);   // [128][132]
#pragma unroll
        for (int i = 0; i < 2; i++) {
            int r0 = wm + 16 * i + g;
#pragma unroll
            for (int nt = 0; nt < 8; nt++) {
                int cc = wn + nt * 8 + tig * 2;
                *reinterpret_cast<float2*>(&ts[r0 * 132 + cc]) =
                    make_float2(c[i][nt][0], c[i][nt][1]);
                *reinterpret_cast<float2*>(&ts[(r0 + 8) * 132 + cc]) =
                    make_float2(c[i][nt][2], c[i][nt][3]);
            }
        }
        __syncthreads();
        const int col = tid & 127;
        const int shalf = (tid >> 7) * 64;
        const int b = m0 >> 11;
        const int sg = (m0 & 2047) + shalf;
        const int hd = (n0 + col) >> 6, d = (n0 + col) & 63;
        size_t obase = ((size_t)((b * 16 + hd) * 64 + d)) * 2048 + sg;
        __nv_bfloat16* vh = Vh + obase;
        __nv_bfloat16* vl = Vl + obase;
#pragma unroll
        for (int t8 = 0; t8 < 8; t8++) {      // 8 s-values per iteration
            uint32_t hb[4], lb[4];
#pragma unroll
            for (int p = 0; p < 4; p++) {
                int sr = shalf + t8 * 8 + 2 * p;
                float v0 = ts[sr * 132 + col];
                float v1 = ts[(sr + 1) * 132 + col];
                split2pack(v0, v1, hb[p], lb[p]);
            }
            *reinterpret_cast<uint4*>(vh + t8 * 8) = make_uint4(hb[0], hb[1], hb[2], hb[3]);
            *reinterpret_cast<uint4*>(vl + t8 * 8) = make_uint4(lb[0], lb[1], lb[2], lb[3]);
        }
    } else {
        // fp32 epilogue (final projection)
#pragma unroll
        for (int i = 0; i < 2; i++) {
            int mrow = m0 + wm + 16 * i + g;
#pragma unroll
            for (int nt = 0; nt < 8; nt++) {
                int col = n0 + wn + nt * 8 + tig * 2;
                float* p = Df + (size_t)mrow * 1024 + col;
                *reinterpret_cast<float2*>(p) = make_float2(c[i][nt][0], c[i][nt][1]);
                *reinterpret_cast<float2*>(p + 8 * 1024) = make_float2(c[i][nt][2], c[i][nt][3]);
            }
        }
    }
}

// ---------------------------------------------------------------------------
// Tensor-core causal flash attention: double-buffered K/V, 2 CTAs/SM,
// exp2-domain softmax (scale folded into Q), fully-masked-warp skip.
// ---------------------------------------------------------------------------
constexpr int ATT_SMEM = 98304;
constexpr uint32_t QH_O = 0, QL_O = 16384, KV_O = 32768;

__global__ void __launch_bounds__(256, 2)
fattn_tc(const __nv_bfloat16* __restrict__ QKh,
         const __nv_bfloat16* __restrict__ QKl,
         const __nv_bfloat16* __restrict__ Vth,
         const __nv_bfloat16* __restrict__ Vtl,
         __nv_bfloat16* __restrict__ Oh, __nv_bfloat16* __restrict__ Ol)
{
    extern __shared__ char smem[];
    const uint32_t sb = smem_to_u32(smem);
    const int tid = threadIdx.x, lane = tid & 31, w = tid >> 5;
    const int qt = (int)gridDim.x - 1 - (int)blockIdx.x;
    const int bh = blockIdx.y;
    const int b = bh >> 4, h = bh & 15;
    const int q0 = qt * 128;
    const int njk = 2 * qt + 2;

    auto issue_kv = [&](int jk, int buf) {
        uint32_t base = sb + KV_O + buf * 32768u;
#pragma unroll
        for (int i = 0; i < 2; i++) {
            int idx = tid + 256 * i;
            int r = idx >> 3, ch = idx & 7;
            uint32_t sw = r * 128 + ((ch ^ (r & 7)) << 4);
            size_t gk = QKV_STRIDE + (size_t)(b * 2048 + jk * 64 + r) * 1024 + h * 64 + ch * 8;
            cp_async16(base + sw,         QKh + gk);
            cp_async16(base + 8192 + sw,  QKl + gk);
            size_t gv = ((size_t)bh * 64 + r) * 2048 + jk * 64 + ch * 8;
            cp_async16(base + 16384 + sw, Vth + gv);
            cp_async16(base + 24576 + sw, Vtl + gv);
        }
        cp_commit();
    };

#pragma unroll
    for (int i = 0; i < 4; i++) {
        int idx = tid + 256 * i;
        int r = idx >> 3, ch = idx & 7;
        size_t gq = (size_t)(b * 2048 + q0 + r) * 1024 + h * 64 + ch * 8;
        uint32_t sw = r * 128 + ((ch ^ (r & 7)) << 4);
        cp_async16(sb + QH_O + sw, QKh + gq);
        cp_async16(sb + QL_O + sw, QKl + gq);
    }
    cp_commit();
    issue_kv(0, 0);

    float o[8][4];
#pragma unroll
    for (int nt = 0; nt < 8; nt++)
#pragma unroll
        for (int q = 0; q < 4; q++) o[nt][q] = 0.f;
    float m0 = -1e30f, m1 = -1e30f, l0 = 0.f, l1 = 0.f;

    const int g_  = lane >> 2, tig = lane & 3;
    const int mrA = w * 16 + ((lane >> 3) & 1) * 8 + (lane & 7);
    const int kcA = (lane >> 4) & 1;
    const int nrB = ((lane >> 4) & 1) * 8 + (lane & 7);
    const int kcB = (lane >> 3) & 1;
    const int row0 = q0 + w * 16 + g_;
    const int wrow_max = q0 + w * 16 + 15;

    for (int jk = 0; jk < njk; jk++) {
        const int buf = jk & 1;
        cp_wait<0>();
        __syncthreads();
        if (jk + 1 < njk) issue_kv(jk + 1, buf ^ 1);

        if (jk * 64 > wrow_max) continue;   // exact no-op: skip

        const uint32_t kbase = sb + KV_O + buf * 32768u;
        const uint32_t vbase = kbase + 16384u;

        float c[8][4];
#pragma unroll
        for (int nt = 0; nt < 8; nt++)
#pragma unroll
            for (int q = 0; q < 4; q++) c[nt][q] = 0.f;

#pragma unroll
        for (int k16 = 0; k16 < 4; k16++) {
            uint32_t ah[4], al[4];
            uint32_t aaddr = sb + QH_O + mrA * 128 +
                ((((k16 << 1) | kcA) ^ (mrA & 7)) << 4);
            ldmx4(ah, aaddr);
            ldmx4(al, aaddr + (QL_O - QH_O));
#pragma unroll
            for (int j = 0; j < 4; j++) {
                int nr = 16 * j + nrB;
                uint32_t baddr = kbase + nr * 128 +
                    ((((k16 << 1) | kcB) ^ (nr & 7)) << 4);
                uint32_t bhh[4], bll[4];
                ldmx4(bhh, baddr);
                ldmx4(bll, baddr + 8192);
                mma_bf16(c[2 * j],     ah, bhh[0], bhh[1]);
                mma_bf16(c[2 * j + 1], ah, bhh[2], bhh[3]);
                mma_bf16(c[2 * j],     al, bhh[0], bhh[1]);
                mma_bf16(c[2 * j + 1], al, bhh[2], bhh[3]);
                mma_bf16(c[2 * j],     ah, bll[0], bll[1]);
                mma_bf16(c[2 * j + 1], ah, bll[2], bll[3]);
            }
        }

        if (jk >= 2 * qt) {
#pragma unroll
            for (int nt = 0; nt < 8; nt++) {
                int colg = jk * 64 + 8 * nt + 2 * tig;
                if (colg     > row0)     c[nt][0] = -1e30f;
                if (colg + 1 > row0)     c[nt][1] = -1e30f;
                if (colg     > row0 + 8) c[nt][2] = -1e30f;
                if (colg + 1 > row0 + 8) c[nt][3] = -1e30f;
            }
        }

        float rm0 = -1e30f, rm1 = -1e30f;
#pragma unroll
        for (int nt = 0; nt < 8; nt++) {
            rm0 = fmaxf(rm0, fmaxf(c[nt][0], c[nt][1]));
            rm1 = fmaxf(rm1, fmaxf(c[nt][2], c[nt][3]));
        }
        rm0 = fmaxf(rm0, __shfl_xor_sync(0xffffffffu, rm0, 1));
        rm0 = fmaxf(rm0, __shfl_xor_sync(0xffffffffu, rm0, 2));
        rm1 = fmaxf(rm1, __shfl_xor_sync(0xffffffffu, rm1, 1));
        rm1 = fmaxf(rm1, __shfl_xor_sync(0xffffffffu, rm1, 2));

        float mn0 = fmaxf(m0, rm0), mn1 = fmaxf(m1, rm1);
        float a0 = ex2f(m0 - mn0), a1 = ex2f(m1 - mn1);
        m0 = mn0; m1 = mn1;

        float rs0 = 0.f, rs1 = 0.f;
#pragma unroll
        for (int nt = 0; nt < 8; nt++) {
            c[nt][0] = ex2f(c[nt][0] - mn0);
            c[nt][1] = ex2f(c[nt][1] - mn0);
            c[nt][2] = ex2f(c[nt][2] - mn1);
            c[nt][3] = ex2f(c[nt][3] - mn1);
            rs0 += c[nt][0] + c[nt][1];
            rs1 += c[nt][2] + c[nt][3];
        }
        rs0 += __shfl_xor_sync(0xffffffffu, rs0, 1);
        rs0 += __shfl_xor_sync(0xffffffffu, rs0, 2);
        rs1 += __shfl_xor_sync(0xffffffffu, rs1, 1);
        rs1 += __shfl_xor_sync(0xffffffffu, rs1, 2);
        l0 = l0 * a0 + rs0;
        l1 = l1 * a1 + rs1;
#pragma unroll
        for (int nt = 0; nt < 8; nt++) {
            o[nt][0] *= a0; o[nt][1] *= a0;
            o[nt][2] *= a1; o[nt][3] *= a1;
        }

#pragma unroll
        for (int k16 = 0; k16 < 4; k16++) {
            uint32_t aph[4], apl[4];
            split2pack(c[2 * k16][0],     c[2 * k16][1],     aph[0], apl[0]);
            split2pack(c[2 * k16][2],     c[2 * k16][3],     aph[1], apl[1]);
            split2pack(c[2 * k16 + 1][0], c[2 * k16 + 1][1], aph[2], apl[2]);
            split2pack(c[2 * k16 + 1][2], c[2 * k16 + 1][3], aph[3], apl[3]);
#pragma unroll
            for (int j = 0; j < 4; j++) {
                int nr = 16 * j + nrB;
                uint32_t baddr = vbase + nr * 128 +
                    ((((k16 << 1) | kcB) ^ (nr & 7)) << 4);
                uint32_t vhh[4], vll[4];
                ldmx4(vhh, baddr);
                ldmx4(vll, baddr + 8192);
                mma_bf16(o[2 * j],     aph, vhh[0], vhh[1]);
                mma_bf16(o[2 * j + 1], aph, vhh[2], vhh[3]);
                mma_bf16(o[2 * j],     apl, vhh[0], vhh[1]);
                mma_bf16(o[2 * j + 1], apl, vhh[2], vhh[3]);
                mma_bf16(o[2 * j],     aph, vll[0], vll[1]);
                mma_bf16(o[2 * j + 1], aph, vll[2], vll[3]);
            }
        }
    }

    float inv0 = 1.0f / l0, inv1 = 1.0f / l1;
    size_t base0 = (size_t)(b * 2048 + row0) * 1024 + h * 64 + 2 * tig;
    size_t base1 = base0 + (size_t)8 * 1024;
#pragma unroll
    for (int nt = 0; nt < 8; nt++) {
        uint32_t hh, ll;
        split2pack(o[nt][0] * inv0, o[nt][1] * inv0, hh, ll);
        *reinterpret_cast<uint32_t*>(Oh + base0 + 8 * nt) = hh;
        *reinterpret_cast<uint32_t*>(Ol + base0 + 8 * nt) = ll;
        split2pack(o[nt][2] * inv1, o[nt][3] * inv1, hh, ll);
        *reinterpret_cast<uint32_t*>(Oh + base1 + 8 * nt) = hh;
        *reinterpret_cast<uint32_t*>(Ol + base1 + 8 * nt) = ll;
    }
}

// ---------------------------------------------------------------------------
extern "C" void kernel_launch(void* const* d_in, const int* in_sizes, int n_in,
                              void* d_out, int out_size)
{
    (void)in_sizes; (void)n_in; (void)out_size;
    const float* x  = (const float*)d_in[0];
    const float* wq = (const float*)d_in[1];
    const float* wk = (const float*)d_in[2];
    const float* wv = (const float*)d_in[3];
    const float* wo = (const float*)d_in[4];
    float* out = (float*)d_out;

    __nv_bfloat16 *pah, *pal, *pwh, *pwl, *pqkh, *pqkl, *pvth, *pvtl;
    cudaGetSymbolAddress((void**)&pah,  g_ah);
    cudaGetSymbolAddress((void**)&pal,  g_al);
    cudaGetSymbolAddress((void**)&pwh,  g_wh);
    cudaGetSymbolAddress((void**)&pwl,  g_wl);
    cudaGetSymbolAddress((void**)&pqkh, g_qkh);
    cudaGetSymbolAddress((void**)&pqkl, g_qkl);
    cudaGetSymbolAddress((void**)&pvth, g_vth);
    cudaGetSymbolAddress((void**)&pvtl, g_vtl);

    cudaFuncSetAttribute(gemm_bf3, cudaFuncAttributeMaxDynamicSharedMemorySize, GEMM_SMEM);
    cudaFuncSetAttribute(fattn_tc, cudaFuncAttributeMaxDynamicSharedMemorySize, ATT_SMEM);

    // Fused prep: rope table (fp32 trig) + x split + w split
    prep_kernel<<<256 + 2048 + 1024, 256>>>(x, wq, wk, wv, wo, pah, pal, pwh, pwl);

    // Fused QKV projection: z=0,1 -> RoPE'd (q pre-scaled) bf16 q/k; z=2 -> V^T bf16
    gemm_bf3<<<dim3(8, 64, 3), 256, GEMM_SMEM>>>(pah, pal, pwh, pwl,
                                                 nullptr, pqkh, pqkl, pvth, pvtl, 1);

    // Attention: writes bf16 hi/lo splits straight into pah/pal
    fattn_tc<<<dim3(16, 64), 256, ATT_SMEM>>>(pqkh, pqkl, pvth, pvtl, pah, pal);

    // Output projection (wo = weight index 3), fp32 out
    gemm_bf3<<<dim3(8, 64, 1), 256, GEMM_SMEM>>>(pah, pal,
        pwh + 3 * W_STRIDE, pwl + 3 * W_STRIDE, out,
        nullptr, nullptr, nullptr, nullptr, 0);
}